// round 1
// baseline (speedup 1.0000x reference)
#include <cuda_runtime.h>
#include <math.h>
#include <stdint.h>

#define BB 64
#define NN 1024
#define CC 256
#define NSAMP 256
#define NH 8
#define HD 32
#define NBH (BB*NH)

#define TM 64
#define KC 16

// ---------------- scratch (static device allocations) ----------------
__device__ float g_xr[BB*NSAMP*CC];          // 4M  floats
__device__ float g_q[NBH*NN*HD];             // 16M floats
__device__ float g_k[NBH*NSAMP*HD];          // 4M
__device__ float g_v[NBH*NSAMP*HD];          // 4M
__device__ float g_kv[NBH*4*HD*HD];          // 2M
__device__ float g_ksum[NBH*4*HD];           // 64K
__device__ float g_attn[BB*NN*CC];           // 16M
__device__ float g_se[BB*CC];                // 16K

// ---------------- SE path: mean over N, 2 tiny FCs, sigmoid ----------------
__global__ __launch_bounds__(256) void se_kernel(
    const float* __restrict__ query,
    const float* __restrict__ w1,
    const float* __restrict__ w2)
{
    const int b = blockIdx.x;
    const int c = threadIdx.x;
    const float* p = query + (size_t)b*CC + c;
    float a0=0.f,a1=0.f,a2=0.f,a3=0.f;
    for (int n = 0; n < NN; n += 4) {
        a0 += p[(size_t)(n+0)*(BB*CC)];
        a1 += p[(size_t)(n+1)*(BB*CC)];
        a2 += p[(size_t)(n+2)*(BB*CC)];
        a3 += p[(size_t)(n+3)*(BB*CC)];
    }
    __shared__ float sm[CC];
    __shared__ float s1[CC/2];
    sm[c] = (a0+a1+a2+a3) * (1.0f/NN);
    __syncthreads();
    if (c < 128) {
        float r = 0.f;
        const float* wr = w1 + (size_t)c*CC;
        #pragma unroll 8
        for (int i = 0; i < CC; i++) r += sm[i]*wr[i];
        s1[c] = fmaxf(r, 0.f);
    }
    __syncthreads();
    {
        float r = 0.f;
        const float* wr = w2 + (size_t)c*128;
        #pragma unroll 8
        for (int j = 0; j < 128; j++) r += s1[j]*wr[j];
        g_se[b*CC + c] = 1.0f / (1.0f + expf(-r));
    }
}

// ---------------- conv 2x2 stride 2 (as GEMM K=1024) + bias + LayerNorm ----------------
__global__ __launch_bounds__(256) void conv_ln_kernel(
    const float* __restrict__ query, const float* __restrict__ srw,
    const float* __restrict__ srb,   const float* __restrict__ ng,
    const float* __restrict__ nbv)
{
    __shared__ __align__(16) float As[KC][TM];
    __shared__ __align__(16) float Ws[KC][CC];
    const int t  = threadIdx.x;
    const int tx = t & 31, ty = t >> 5;
    const int r0 = blockIdx.x * TM;
    const int b  = r0 >> 8;                    // 256 rows per batch
    const int arow = t & 63;
    const int akk  = (t >> 6) * 4;
    const int grA  = r0 + arow;
    const int nsA  = grA & 255;
    const int pixbase = ((nsA >> 4) * 2) * 32 + (nsA & 15) * 2;

    float acc[8][8];
    #pragma unroll
    for (int i = 0; i < 8; i++)
        #pragma unroll
        for (int j = 0; j < 8; j++) acc[i][j] = 0.f;

    for (int ch = 0; ch < 64; ch++) {
        const int k0  = ch * KC;
        const int p   = k0 >> 8;               // kernel tap 0..3
        const int ci0 = k0 & 255;
        const int pix = pixbase + (p >> 1) * 32 + (p & 1);
        float4 av = *(const float4*)(query + (size_t)pix*(BB*CC) + b*CC + ci0 + akk);
        As[akk+0][arow] = av.x; As[akk+1][arow] = av.y;
        As[akk+2][arow] = av.z; As[akk+3][arow] = av.w;
        const float* wp = srw + (size_t)t*1024 + ci0*4 + p;
        #pragma unroll
        for (int kk = 0; kk < KC; kk++) Ws[kk][t] = wp[kk*4];
        __syncthreads();
        #pragma unroll
        for (int kk = 0; kk < KC; kk++) {
            float4 a0 = *(const float4*)&As[kk][ty*8];
            float4 a1 = *(const float4*)&As[kk][ty*8+4];
            float4 w0 = *(const float4*)&Ws[kk][tx*8];
            float4 w1 = *(const float4*)&Ws[kk][tx*8+4];
            float ar[8] = {a0.x,a0.y,a0.z,a0.w,a1.x,a1.y,a1.z,a1.w};
            float wr[8] = {w0.x,w0.y,w0.z,w0.w,w1.x,w1.y,w1.z,w1.w};
            #pragma unroll
            for (int i = 0; i < 8; i++)
                #pragma unroll
                for (int j = 0; j < 8; j++)
                    acc[i][j] += ar[i]*wr[j];
        }
        __syncthreads();
    }
    float bj[8], gj[8], betaj[8];
    #pragma unroll
    for (int j = 0; j < 8; j++) {
        bj[j] = srb[tx*8+j]; gj[j] = ng[tx*8+j]; betaj[j] = nbv[tx*8+j];
    }
    #pragma unroll
    for (int i = 0; i < 8; i++) {
        float s = 0.f, sq = 0.f;
        #pragma unroll
        for (int j = 0; j < 8; j++) {
            float v = acc[i][j] + bj[j];
            acc[i][j] = v; s += v; sq += v*v;
        }
        #pragma unroll
        for (int off = 16; off > 0; off >>= 1) {
            s  += __shfl_xor_sync(0xffffffffu, s, off);
            sq += __shfl_xor_sync(0xffffffffu, sq, off);
        }
        const float mu  = s * (1.f/CC);
        const float inv = rsqrtf(sq*(1.f/CC) - mu*mu + 1e-5f);
        const int row = r0 + ty*8 + i;
        float o[8];
        #pragma unroll
        for (int j = 0; j < 8; j++) o[j] = (acc[i][j]-mu)*inv*gj[j] + betaj[j];
        float4* dst = (float4*)(g_xr + (size_t)row*CC + tx*8);
        dst[0] = make_float4(o[0],o[1],o[2],o[3]);
        dst[1] = make_float4(o[4],o[5],o[6],o[7]);
    }
}

// ---------------- generic 64x256 x K=256 projection GEMM with fused epilogues ----------------
// ASRC: 0 = gather from query (row = b*1024+n -> query[n,b,:]); 1 = g_xr; 2 = g_attn
// EMODE: 0 = k (relu, split-head store to g_k); 1 = v (split-head store to g_v);
//        2 = q (scale+relu, split-head store to g_q); 3 = out (SE gate, scatter to (n,b,c))
template<int ASRC, int EMODE>
__global__ __launch_bounds__(256) void proj_kernel(
    const float* __restrict__ Ain, const float* __restrict__ W,
    const float* __restrict__ bias, float* __restrict__ outp,
    int Lrows)
{
    __shared__ __align__(16) float As[KC][TM];
    __shared__ __align__(16) float Ws[KC][CC];
    const int t  = threadIdx.x;
    const int tx = t & 31, ty = t >> 5;
    const int r0 = blockIdx.x * TM;
    const int arow = t & 63;
    const int akk  = (t >> 6) * 4;
    const int grA  = r0 + arow;

    const float* Abase;
    if (ASRC == 0) {
        const int bA = grA >> 10, nA = grA & 1023;
        Abase = Ain + (size_t)nA*(BB*CC) + bA*CC;
    } else if (ASRC == 1) {
        Abase = g_xr + (size_t)grA*CC;
    } else {
        Abase = g_attn + (size_t)grA*CC;
    }

    float acc[8][8];
    #pragma unroll
    for (int i = 0; i < 8; i++)
        #pragma unroll
        for (int j = 0; j < 8; j++) acc[i][j] = 0.f;

    for (int ch = 0; ch < CC/KC; ch++) {
        const int k0 = ch*KC;
        float4 av = *(const float4*)(Abase + k0 + akk);
        As[akk+0][arow] = av.x; As[akk+1][arow] = av.y;
        As[akk+2][arow] = av.z; As[akk+3][arow] = av.w;
        const float4* wp = (const float4*)(W + (size_t)t*CC + k0);
        #pragma unroll
        for (int q4 = 0; q4 < 4; q4++) {
            float4 w = wp[q4];
            Ws[q4*4+0][t]=w.x; Ws[q4*4+1][t]=w.y; Ws[q4*4+2][t]=w.z; Ws[q4*4+3][t]=w.w;
        }
        __syncthreads();
        #pragma unroll
        for (int kk = 0; kk < KC; kk++) {
            float4 a0 = *(const float4*)&As[kk][ty*8];
            float4 a1 = *(const float4*)&As[kk][ty*8+4];
            float4 w0 = *(const float4*)&Ws[kk][tx*8];
            float4 w1 = *(const float4*)&Ws[kk][tx*8+4];
            float ar[8] = {a0.x,a0.y,a0.z,a0.w,a1.x,a1.y,a1.z,a1.w};
            float wr[8] = {w0.x,w0.y,w0.z,w0.w,w1.x,w1.y,w1.z,w1.w};
            #pragma unroll
            for (int i = 0; i < 8; i++)
                #pragma unroll
                for (int j = 0; j < 8; j++)
                    acc[i][j] += ar[i]*wr[j];
        }
        __syncthreads();
    }

    const int b     = r0 / Lrows;
    const int nbase = r0 % Lrows;
    float b8[8];
    #pragma unroll
    for (int j = 0; j < 8; j++) b8[j] = bias[tx*8+j];

    if (EMODE == 3) {
        float s8[8];
        #pragma unroll
        for (int j = 0; j < 8; j++) s8[j] = g_se[b*CC + tx*8 + j];
        #pragma unroll
        for (int i = 0; i < 8; i++) {
            const int n = nbase + ty*8 + i;
            float o[8];
            #pragma unroll
            for (int j = 0; j < 8; j++) o[j] = (acc[i][j]+b8[j])*s8[j];
            float4* dst = (float4*)(outp + (size_t)n*(BB*CC) + b*CC + tx*8);
            dst[0] = make_float4(o[0],o[1],o[2],o[3]);
            dst[1] = make_float4(o[4],o[5],o[6],o[7]);
        }
    } else {
        const int h  = tx >> 2;
        const int d0 = (tx*8) & 31;
        float* gb = (EMODE==2) ? g_q : ((EMODE==0) ? g_k : g_v);
        #pragma unroll
        for (int i = 0; i < 8; i++) {
            const int n = nbase + ty*8 + i;
            float o[8];
            #pragma unroll
            for (int j = 0; j < 8; j++) {
                float v = acc[i][j] + b8[j];
                if (EMODE == 2) v = fmaxf(v*0.17677669529663687f, 0.f);
                if (EMODE == 0) v = fmaxf(v, 0.f);
                o[j] = v;
            }
            float4* dst = (float4*)(gb + ((size_t)(b*NH + h)*Lrows + n)*HD + d0);
            dst[0] = make_float4(o[0],o[1],o[2],o[3]);
            dst[1] = make_float4(o[4],o[5],o[6],o[7]);
        }
    }
}

// ---------------- kv accumulation: kv[g][d][m] = sum_n w_g[n] k[n][d] v[n][m]; ksum ----------------
__global__ __launch_bounds__(256) void kv_kernel()
{
    const int bh = blockIdx.x;
    const int t  = threadIdx.x;
    const int m  = t & 31, dq = t >> 5;     // dq 0..7
    __shared__ __align__(16) float ks[128*32];
    __shared__ __align__(16) float vs[128*32];
    __shared__ float wsm[4][128];
    float acc[4][4];
    #pragma unroll
    for (int g = 0; g < 4; g++)
        #pragma unroll
        for (int di = 0; di < 4; di++) acc[g][di] = 0.f;
    float ksacc = 0.f;

    for (int half = 0; half < 2; half++) {
        __syncthreads();
        const float4* kp = (const float4*)(g_k + ((size_t)bh*NSAMP + half*128)*HD);
        const float4* vp = (const float4*)(g_v + ((size_t)bh*NSAMP + half*128)*HD);
        float4* ks4 = (float4*)ks;
        float4* vs4 = (float4*)vs;
        #pragma unroll
        for (int i = 0; i < 4; i++) {
            ks4[t + i*256] = kp[t + i*256];
            vs4[t + i*256] = vp[t + i*256];
        }
        if (t < 128) {
            const int ns = half*128 + t;
            const float aa = 1.57079632679489662f * (float)(ns >> 4) * (1.f/16.f);
            const float ab = 1.57079632679489662f * (float)(ns & 15) * (1.f/16.f);
            wsm[0][t] = cosf(aa); wsm[1][t] = sinf(aa);
            wsm[2][t] = cosf(ab); wsm[3][t] = sinf(ab);
        }
        __syncthreads();
        #pragma unroll 4
        for (int nl = 0; nl < 128; nl++) {
            const float wv = vs[nl*32 + m];
            float4 kd = *(const float4*)&ks[nl*32 + dq*4];
            float w0 = wsm[0][nl]*wv, w1 = wsm[1][nl]*wv;
            float w2 = wsm[2][nl]*wv, w3 = wsm[3][nl]*wv;
            acc[0][0]+=kd.x*w0; acc[0][1]+=kd.y*w0; acc[0][2]+=kd.z*w0; acc[0][3]+=kd.w*w0;
            acc[1][0]+=kd.x*w1; acc[1][1]+=kd.y*w1; acc[1][2]+=kd.z*w1; acc[1][3]+=kd.w*w1;
            acc[2][0]+=kd.x*w2; acc[2][1]+=kd.y*w2; acc[2][2]+=kd.z*w2; acc[2][3]+=kd.w*w2;
            acc[3][0]+=kd.x*w3; acc[3][1]+=kd.y*w3; acc[3][2]+=kd.z*w3; acc[3][3]+=kd.w*w3;
        }
        if (t < 128) {
            const int g = t >> 5, d = t & 31;
            float s = 0.f;
            #pragma unroll 8
            for (int nl = 0; nl < 128; nl++) s += wsm[g][nl] * ks[nl*32 + d];
            ksacc += s;
        }
    }
    float* kvp = g_kv + (size_t)bh*4096;
    #pragma unroll
    for (int g = 0; g < 4; g++)
        #pragma unroll
        for (int di = 0; di < 4; di++)
            kvp[(g*32 + dq*4 + di)*32 + m] = acc[g][di];
    if (t < 128) g_ksum[bh*128 + t] = ksacc;
}

// ---------------- per-query attention: attn[n][m] = (sum_g u_g q . kv_g[:,m]) / clamp(denom) ----------------
__global__ __launch_bounds__(256) void attn_kernel()
{
    const int bh = blockIdx.y;
    const int nt = blockIdx.x;
    const int t  = threadIdx.x;
    __shared__ __align__(16) float kvs[4096];
    __shared__ float ksums[128];
    {
        const float4* kp = (const float4*)(g_kv + (size_t)bh*4096);
        float4* d4 = (float4*)kvs;
        #pragma unroll
        for (int i = 0; i < 4; i++) d4[t + i*256] = kp[t + i*256];
        if (t < 128) ksums[t] = g_ksum[bh*128 + t];
    }
    __syncthreads();

    const int n = nt*256 + t;
    const float* qp = g_q + ((size_t)bh*NN + n)*HD;
    float q[32];
    #pragma unroll
    for (int i = 0; i < 8; i++) {
        float4 v = ((const float4*)qp)[i];
        q[i*4+0]=v.x; q[i*4+1]=v.y; q[i*4+2]=v.z; q[i*4+3]=v.w;
    }
    const float aa = 1.57079632679489662f * (float)(n >> 5) * (1.f/32.f);
    const float ab = 1.57079632679489662f * (float)(n & 31) * (1.f/32.f);
    float u[4]; u[0]=cosf(aa); u[1]=sinf(aa); u[2]=cosf(ab); u[3]=sinf(ab);

    float den = 0.f;
    #pragma unroll
    for (int g = 0; g < 4; g++) {
        float s = 0.f;
        #pragma unroll
        for (int d = 0; d < 32; d++) s += q[d]*ksums[g*32+d];
        den += u[g]*s;
    }
    float ad = fminf(fmaxf(fabsf(den), 1e-4f), 1e4f);
    const float inv = 1.0f / copysignf(ad, den);

    float4 acc[8];
    #pragma unroll
    for (int i = 0; i < 8; i++) acc[i] = make_float4(0.f,0.f,0.f,0.f);
    for (int g = 0; g < 4; g++) {
        const float ug = u[g];
        const float4* kvg = (const float4*)(kvs + g*1024);
        #pragma unroll 4
        for (int d = 0; d < 32; d++) {
            const float coef = ug * q[d];
            #pragma unroll
            for (int mq = 0; mq < 8; mq++) {
                float4 kvv = kvg[d*8 + mq];
                acc[mq].x += coef*kvv.x; acc[mq].y += coef*kvv.y;
                acc[mq].z += coef*kvv.z; acc[mq].w += coef*kvv.w;
            }
        }
    }
    const int b = bh >> 3, h = bh & 7;
    float4* op = (float4*)(g_attn + ((size_t)b*NN + n)*CC + h*HD);
    #pragma unroll
    for (int mq = 0; mq < 8; mq++) {
        acc[mq].x *= inv; acc[mq].y *= inv; acc[mq].z *= inv; acc[mq].w *= inv;
        op[mq] = acc[mq];
    }
}

// ---------------- launch ----------------
extern "C" void kernel_launch(void* const* d_in, const int* in_sizes, int n_in,
                              void* d_out, int out_size)
{
    const float *query=nullptr, *ipw=nullptr, *ipb=nullptr, *srw=nullptr, *srb=nullptr,
                *ng=nullptr, *nb=nullptr, *outw=nullptr, *outb=nullptr,
                *sew1=nullptr, *sew2=nullptr;
    int nbig = 0, n256 = 0, n32k = 0;
    for (int i = 0; i < n_in; i++) {
        const int s = in_sizes[i];
        const float* p = (const float*)d_in[i];
        if (s == 16777216)      { if (nbig++ == 0) query = p; }        // query, key, value
        else if (s == 196608)   ipw = p;                               // in_proj_weight
        else if (s == 768)      ipb = p;                               // in_proj_bias
        else if (s == 262144)   srw = p;                               // sr_w
        else if (s == 65536)    outw = p;                              // out_w
        else if (s == 32768)    { if (n32k++ == 0) sew1 = p; else sew2 = p; }
        else if (s == 256) {
            switch (n256++) {
                case 0: srb = p; break;  // sr_b
                case 1: ng  = p; break;  // norm_g
                case 2: nb  = p; break;  // norm_b
                case 3: outb= p; break;  // out_b
            }
        }
    }
    float* out = (float*)d_out;

    se_kernel<<<BB, 256>>>(query, sew1, sew2);
    conv_ln_kernel<<<(BB*NSAMP)/TM, 256>>>(query, srw, srb, ng, nb);
    proj_kernel<0,2><<<(BB*NN)/TM,    256>>>(query,   ipw,            ipb,        nullptr, NN);
    proj_kernel<1,0><<<(BB*NSAMP)/TM, 256>>>(nullptr, ipw + CC*CC,    ipb + CC,   nullptr, NSAMP);
    proj_kernel<1,1><<<(BB*NSAMP)/TM, 256>>>(nullptr, ipw + 2*CC*CC,  ipb + 2*CC, nullptr, NSAMP);
    kv_kernel<<<NBH, 256>>>();
    attn_kernel<<<dim3(4, NBH), 256>>>();
    proj_kernel<2,3><<<(BB*NN)/TM, 256>>>(nullptr, outw, outb, out, NN);
    (void)out_size;
}

// round 6
// speedup vs baseline: 1.5037x; 1.5037x over previous
#include <cuda_runtime.h>
#include <math.h>
#include <stdint.h>

#define BB 64
#define NN 1024
#define CC 256
#define NSAMP 256
#define NH 8
#define HD 32
#define NBH (BB*NH)

__device__ float g_xr[BB*NSAMP*CC];
__device__ float g_q[NBH*NN*HD];
__device__ float g_k[NBH*NSAMP*HD];
__device__ float g_v[NBH*NSAMP*HD];
__device__ float g_kv[NBH*4*HD*HD];
__device__ float g_ksum[NBH*4*HD];
__device__ float g_attn[BB*NN*CC];
__device__ float g_se[BB*CC];
__device__ float g_wc_hi[256*1024];
__device__ float g_wc_lo[256*1024];
__device__ float g_wp_hi[4*256*256];
__device__ float g_wp_lo[4*256*256];

__device__ __forceinline__ void split_tf32(float a, float& hi, float& lo) {
    uint32_t u;
    asm("cvt.rna.tf32.f32 %0, %1;" : "=r"(u) : "f"(a));
    hi = __uint_as_float(u);
    lo = a - hi;
}

__device__ __forceinline__ void mma8(float* d, const float* a, const float* b) {
    asm volatile(
        "mma.sync.aligned.m16n8k8.row.col.f32.tf32.tf32.f32 "
        "{%0,%1,%2,%3}, {%4,%5,%6,%7}, {%8,%9}, {%0,%1,%2,%3};"
        : "+f"(d[0]), "+f"(d[1]), "+f"(d[2]), "+f"(d[3])
        : "r"(__float_as_uint(a[0])), "r"(__float_as_uint(a[1])),
          "r"(__float_as_uint(a[2])), "r"(__float_as_uint(a[3])),
          "r"(__float_as_uint(b[0])), "r"(__float_as_uint(b[1])));
}

// ---------------- weight prep: reorder + hi/lo split ----------------
__global__ __launch_bounds__(256) void prep_kernel(
    const float* __restrict__ ipw, const float* __restrict__ outw,
    const float* __restrict__ srw)
{
    int idx = blockIdx.x*256 + threadIdx.x;
    if (idx < 262144) {
        int oc = idx >> 10, k = idx & 1023, p = k >> 8, ci = k & 255;
        float v = srw[oc*1024 + ci*4 + p];
        float h, l; split_tf32(v, h, l);
        g_wc_hi[idx] = h; g_wc_lo[idx] = l;
    } else {
        int j = idx - 262144;
        int m = j >> 16;
        const float* src = (m < 3) ? (ipw + m*65536) : outw;
        float v = src[j & 65535];
        float h, l; split_tf32(v, h, l);
        g_wp_hi[j] = h; g_wp_lo[j] = l;
    }
}

// ---------------- SE ----------------
__global__ __launch_bounds__(256) void se_kernel(
    const float* __restrict__ query, const float* __restrict__ w1,
    const float* __restrict__ w2)
{
    const int b = blockIdx.x, c = threadIdx.x;
    const float* p = query + (size_t)b*CC + c;
    float a0=0.f,a1=0.f,a2=0.f,a3=0.f;
    for (int n = 0; n < NN; n += 4) {
        a0 += p[(size_t)(n+0)*(BB*CC)];
        a1 += p[(size_t)(n+1)*(BB*CC)];
        a2 += p[(size_t)(n+2)*(BB*CC)];
        a3 += p[(size_t)(n+3)*(BB*CC)];
    }
    __shared__ float sm[CC];
    __shared__ float s1[CC/2];
    sm[c] = (a0+a1+a2+a3) * (1.0f/NN);
    __syncthreads();
    if (c < 128) {
        float r = 0.f;
        const float* wr = w1 + (size_t)c*CC;
        #pragma unroll 8
        for (int i = 0; i < CC; i++) r += sm[i]*wr[i];
        s1[c] = fmaxf(r, 0.f);
    }
    __syncthreads();
    {
        float r = 0.f;
        const float* wr = w2 + (size_t)c*128;
        #pragma unroll 8
        for (int j = 0; j < 128; j++) r += s1[j]*wr[j];
        g_se[b*CC + c] = 1.0f / (1.0f + expf(-r));
    }
}

// =======================================================================
// mma.sync tf32 GEMM, 3-term hi/lo split.
// ASRC: 0=query gather (row=b*1024+n), 1=g_xr, 2=g_attn, 3=conv gather
// EMODE: 0=k(relu,split-head) 1=v(split-head) 2=q(scale+relu,split-head)
//        3=out(SE gate scatter) 4=conv(bias+LayerNorm -> g_xr)
// =======================================================================
template<int ASRC, int EMODE, int WSEL, int MTILE, int NTOT, int KTOT, int LB>
__global__ __launch_bounds__(256, 1) void mm_tc(
    const float* __restrict__ Ain, const float* __restrict__ bias,
    const float* __restrict__ aux0, const float* __restrict__ aux1,
    float* __restrict__ outp)
{
    constexpr int WM = MTILE/32;        // warps along M
    constexpr int LROWS = 1<<LB;
    extern __shared__ float smf[];
    float* sAhi = smf;
    float* sAlo = smf + MTILE*36;
    float* sWhi = smf + 2*MTILE*36;
    float* sWlo = smf + 2*MTILE*36 + NTOT*36;

    const int t = threadIdx.x, lane = t & 31, wid = t >> 5;
    const int g = lane >> 2, t4 = lane & 3;
    const int warp_m = wid & (WM-1);
    const int warp_n = wid / WM;
    const int ncol0 = blockIdx.y * NTOT;
    const int grow0 = blockIdx.x * MTILE;

    const float* Whi_src = (ASRC==3) ? g_wc_hi : (g_wp_hi + WSEL*65536);
    const float* Wlo_src = (ASRC==3) ? g_wc_lo : (g_wp_lo + WSEL*65536);

    float acc[2][8][4];
    #pragma unroll
    for (int mt=0; mt<2; mt++)
        #pragma unroll
        for (int nt=0; nt<8; nt++)
            #pragma unroll
            for (int q=0; q<4; q++) acc[mt][nt][q] = 0.f;

    constexpr int NCH = KTOT/32;
    for (int c = 0; c < NCH; c++) {
        // ---- stage A (hi/lo on the fly) ----
        #pragma unroll
        for (int i = 0; i < MTILE/32; i++) {
            int idx = t + i*256;
            int row = idx >> 3, q4 = idx & 7;
            int r = grow0 + row;
            const float* p;
            if (ASRC == 3) {
                int b = r >> 8, ns = r & 255;
                int py = (ns >> 4)*2, px = (ns & 15)*2;
                int pp = c >> 3, ci0 = (c & 7)*32;
                int pix = (py + (pp>>1))*32 + px + (pp&1);
                p = Ain + (size_t)pix*(BB*CC) + b*CC + ci0 + q4*4;
            } else if (ASRC == 0) {
                p = Ain + (size_t)(r & (LROWS-1))*(BB*CC) + (r>>LB)*CC + c*32 + q4*4;
            } else {
                const float* base = (ASRC==1) ? g_xr : g_attn;
                p = base + (size_t)r*CC + c*32 + q4*4;
            }
            float4 v = *(const float4*)p;
            float h0,h1,h2,h3,l0,l1,l2,l3;
            split_tf32(v.x,h0,l0); split_tf32(v.y,h1,l1);
            split_tf32(v.z,h2,l2); split_tf32(v.w,h3,l3);
            int off = row*36 + q4*4;
            *(float4*)(sAhi+off) = make_float4(h0,h1,h2,h3);
            *(float4*)(sAlo+off) = make_float4(l0,l1,l2,l3);
        }
        // ---- stage W (pre-split) ----
        #pragma unroll
        for (int i = 0; i < NTOT/32; i++) {
            int idx = t + i*256;
            int row = idx >> 3, q4 = idx & 7;
            size_t go = (size_t)(ncol0 + row)*KTOT + c*32 + q4*4;
            int off = row*36 + q4*4;
            *(float4*)(sWhi+off) = *(const float4*)(Whi_src + go);
            *(float4*)(sWlo+off) = *(const float4*)(Wlo_src + go);
        }
        __syncthreads();
        // ---- 4 k-steps of 8 ----
        #pragma unroll
        for (int ks = 0; ks < 4; ks++) {
            const int k0 = ks*8;
            float ah[2][4], al[2][4];
            #pragma unroll
            for (int mt=0; mt<2; mt++) {
                int rb = (warp_m*32 + mt*16 + g)*36 + k0 + t4;
                ah[mt][0]=sAhi[rb];       ah[mt][1]=sAhi[rb+288];
                ah[mt][2]=sAhi[rb+4];     ah[mt][3]=sAhi[rb+292];
                al[mt][0]=sAlo[rb];       al[mt][1]=sAlo[rb+288];
                al[mt][2]=sAlo[rb+4];     al[mt][3]=sAlo[rb+292];
            }
            #pragma unroll
            for (int nt=0; nt<8; nt++) {
                int nb = (warp_n*64 + nt*8 + g)*36 + k0 + t4;
                float bh[2], bl[2];
                bh[0]=sWhi[nb]; bh[1]=sWhi[nb+4];
                bl[0]=sWlo[nb]; bl[1]=sWlo[nb+4];
                #pragma unroll
                for (int mt=0; mt<2; mt++) {
                    mma8(acc[mt][nt], ah[mt], bh);
                    mma8(acc[mt][nt], ah[mt], bl);
                    mma8(acc[mt][nt], al[mt], bh);
                }
            }
        }
        __syncthreads();
    }

    // ================= epilogues =================
    if (EMODE == 4) {
        __shared__ float lnp[64][4], lnq[64][4], lnmu[64], lniv[64];
        float ps[2][2] = {{0.f,0.f},{0.f,0.f}};
        float pq[2][2] = {{0.f,0.f},{0.f,0.f}};
        #pragma unroll
        for (int mt=0; mt<2; mt++)
            #pragma unroll
            for (int nt=0; nt<8; nt++) {
                int gcol = warp_n*64 + nt*8 + t4*2;
                float2 bb = *(const float2*)(bias + gcol);
                float v0=acc[mt][nt][0]+bb.x, v1=acc[mt][nt][1]+bb.y;
                float v2=acc[mt][nt][2]+bb.x, v3=acc[mt][nt][3]+bb.y;
                acc[mt][nt][0]=v0; acc[mt][nt][1]=v1;
                acc[mt][nt][2]=v2; acc[mt][nt][3]=v3;
                ps[mt][0]+=v0+v1; pq[mt][0]+=v0*v0+v1*v1;
                ps[mt][1]+=v2+v3; pq[mt][1]+=v2*v2+v3*v3;
            }
        #pragma unroll
        for (int mt=0; mt<2; mt++)
            #pragma unroll
            for (int hf=0; hf<2; hf++) {
                float s = ps[mt][hf], q = pq[mt][hf];
                s += __shfl_xor_sync(0xffffffffu, s, 1);
                s += __shfl_xor_sync(0xffffffffu, s, 2);
                q += __shfl_xor_sync(0xffffffffu, q, 1);
                q += __shfl_xor_sync(0xffffffffu, q, 2);
                if (t4 == 0) {
                    int row = warp_m*32 + mt*16 + g + hf*8;
                    lnp[row][warp_n] = s; lnq[row][warp_n] = q;
                }
            }
        __syncthreads();
        if (t < 64) {
            float s = lnp[t][0]+lnp[t][1]+lnp[t][2]+lnp[t][3];
            float q = lnq[t][0]+lnq[t][1]+lnq[t][2]+lnq[t][3];
            float mu = s*(1.f/256.f);
            lnmu[t] = mu;
            lniv[t] = rsqrtf(q*(1.f/256.f) - mu*mu + 1e-5f);
        }
        __syncthreads();
        #pragma unroll
        for (int mt=0; mt<2; mt++) {
            int ra = warp_m*32 + mt*16 + g;
            float mua = lnmu[ra],   iva = lniv[ra];
            float mub = lnmu[ra+8], ivb = lniv[ra+8];
            #pragma unroll
            for (int nt=0; nt<8; nt++) {
                int gcol = warp_n*64 + nt*8 + t4*2;
                float2 gv = *(const float2*)(aux0 + gcol);
                float2 bv = *(const float2*)(aux1 + gcol);
                float o0 = (acc[mt][nt][0]-mua)*iva*gv.x + bv.x;
                float o1 = (acc[mt][nt][1]-mua)*iva*gv.y + bv.y;
                float o2 = (acc[mt][nt][2]-mub)*ivb*gv.x + bv.x;
                float o3 = (acc[mt][nt][3]-mub)*ivb*gv.y + bv.y;
                *(float2*)(g_xr + (size_t)(grow0+ra)*CC + gcol)   = make_float2(o0,o1);
                *(float2*)(g_xr + (size_t)(grow0+ra+8)*CC + gcol) = make_float2(o2,o3);
            }
        }
    } else {
        #pragma unroll
        for (int mt=0; mt<2; mt++) {
            int r1 = grow0 + warp_m*32 + mt*16 + g;
            int b1 = r1 >> LB;
            int n1 = r1 & (LROWS-1);
            int n2 = n1 + 8;
            #pragma unroll
            for (int nt=0; nt<8; nt++) {
                int gcol = ncol0 + warp_n*64 + nt*8 + t4*2;
                float2 bb = *(const float2*)(bias + gcol);
                float v0=acc[mt][nt][0]+bb.x, v1=acc[mt][nt][1]+bb.y;
                float v2=acc[mt][nt][2]+bb.x, v3=acc[mt][nt][3]+bb.y;
                if (EMODE == 2) {
                    const float sc = 0.17677669529663687f;
                    v0=fmaxf(v0*sc,0.f); v1=fmaxf(v1*sc,0.f);
                    v2=fmaxf(v2*sc,0.f); v3=fmaxf(v3*sc,0.f);
                }
                if (EMODE == 0) {
                    v0=fmaxf(v0,0.f); v1=fmaxf(v1,0.f);
                    v2=fmaxf(v2,0.f); v3=fmaxf(v3,0.f);
                }
                if (EMODE == 3) {
                    float2 se = *(const float2*)(g_se + b1*CC + gcol);
                    *(float2*)(outp + ((size_t)n1*BB + b1)*CC + gcol) = make_float2(v0*se.x, v1*se.y);
                    *(float2*)(outp + ((size_t)n2*BB + b1)*CC + gcol) = make_float2(v2*se.x, v3*se.y);
                } else {
                    int h = gcol >> 5, d = gcol & 31;
                    float* gb = (EMODE==2) ? g_q : ((EMODE==0) ? g_k : g_v);
                    size_t base = ((size_t)(b1*NH + h) << LB);
                    *(float2*)(gb + (base + n1)*HD + d) = make_float2(v0,v1);
                    *(float2*)(gb + (base + n2)*HD + d) = make_float2(v2,v3);
                }
            }
        }
    }
}

// ---------------- kv accumulation ----------------
__global__ __launch_bounds__(256) void kv_kernel()
{
    const int bh = blockIdx.x;
    const int t  = threadIdx.x;
    const int m  = t & 31, dq = t >> 5;
    __shared__ __align__(16) float ks[128*32];
    __shared__ __align__(16) float vs[128*32];
    __shared__ float wsm[4][128];
    float acc[4][4];
    #pragma unroll
    for (int g = 0; g < 4; g++)
        #pragma unroll
        for (int di = 0; di < 4; di++) acc[g][di] = 0.f;
    float ksacc = 0.f;

    for (int half = 0; half < 2; half++) {
        __syncthreads();
        const float4* kp = (const float4*)(g_k + ((size_t)bh*NSAMP + half*128)*HD);
        const float4* vp = (const float4*)(g_v + ((size_t)bh*NSAMP + half*128)*HD);
        float4* ks4 = (float4*)ks;
        float4* vs4 = (float4*)vs;
        #pragma unroll
        for (int i = 0; i < 4; i++) {
            ks4[t + i*256] = kp[t + i*256];
            vs4[t + i*256] = vp[t + i*256];
        }
        if (t < 128) {
            const int ns = half*128 + t;
            const float aa = 1.57079632679489662f * (float)(ns >> 4) * (1.f/16.f);
            const float ab = 1.57079632679489662f * (float)(ns & 15) * (1.f/16.f);
            wsm[0][t] = cosf(aa); wsm[1][t] = sinf(aa);
            wsm[2][t] = cosf(ab); wsm[3][t] = sinf(ab);
        }
        __syncthreads();
        #pragma unroll 4
        for (int nl = 0; nl < 128; nl++) {
            const float wv = vs[nl*32 + m];
            float4 kd = *(const float4*)&ks[nl*32 + dq*4];
            float w0 = wsm[0][nl]*wv, w1 = wsm[1][nl]*wv;
            float w2 = wsm[2][nl]*wv, w3 = wsm[3][nl]*wv;
            acc[0][0]+=kd.x*w0; acc[0][1]+=kd.y*w0; acc[0][2]+=kd.z*w0; acc[0][3]+=kd.w*w0;
            acc[1][0]+=kd.x*w1; acc[1][1]+=kd.y*w1; acc[1][2]+=kd.z*w1; acc[1][3]+=kd.w*w1;
            acc[2][0]+=kd.x*w2; acc[2][1]+=kd.y*w2; acc[2][2]+=kd.z*w2; acc[2][3]+=kd.w*w2;
            acc[3][0]+=kd.x*w3; acc[3][1]+=kd.y*w3; acc[3][2]+=kd.z*w3; acc[3][3]+=kd.w*w3;
        }
        if (t < 128) {
            const int g = t >> 5, d = t & 31;
            float s = 0.f;
            #pragma unroll 8
            for (int nl = 0; nl < 128; nl++) s += wsm[g][nl] * ks[nl*32 + d];
            ksacc += s;
        }
    }
    float* kvp = g_kv + (size_t)bh*4096;
    #pragma unroll
    for (int g = 0; g < 4; g++)
        #pragma unroll
        for (int di = 0; di < 4; di++)
            kvp[(g*32 + dq*4 + di)*32 + m] = acc[g][di];
    if (t < 128) g_ksum[bh*128 + t] = ksacc;
}

// ---------------- per-query attention ----------------
__global__ __launch_bounds__(256) void attn_kernel()
{
    const int bh = blockIdx.y;
    const int nt = blockIdx.x;
    const int t  = threadIdx.x;
    __shared__ __align__(16) float kvs[4096];
    __shared__ float ksums[128];
    {
        const float4* kp = (const float4*)(g_kv + (size_t)bh*4096);
        float4* d4 = (float4*)kvs;
        #pragma unroll
        for (int i = 0; i < 4; i++) d4[t + i*256] = kp[t + i*256];
        if (t < 128) ksums[t] = g_ksum[bh*128 + t];
    }
    __syncthreads();

    const int n = nt*256 + t;
    const float* qp = g_q + ((size_t)bh*NN + n)*HD;
    float q[32];
    #pragma unroll
    for (int i = 0; i < 8; i++) {
        float4 v = ((const float4*)qp)[i];
        q[i*4+0]=v.x; q[i*4+1]=v.y; q[i*4+2]=v.z; q[i*4+3]=v.w;
    }
    const float aa = 1.57079632679489662f * (float)(n >> 5) * (1.f/32.f);
    const float ab = 1.57079632679489662f * (float)(n & 31) * (1.f/32.f);
    float u[4]; u[0]=cosf(aa); u[1]=sinf(aa); u[2]=cosf(ab); u[3]=sinf(ab);

    float den = 0.f;
    #pragma unroll
    for (int g = 0; g < 4; g++) {
        float s = 0.f;
        #pragma unroll
        for (int d = 0; d < 32; d++) s += q[d]*ksums[g*32+d];
        den += u[g]*s;
    }
    float ad = fminf(fmaxf(fabsf(den), 1e-4f), 1e4f);
    const float inv = 1.0f / copysignf(ad, den);

    float4 acc[8];
    #pragma unroll
    for (int i = 0; i < 8; i++) acc[i] = make_float4(0.f,0.f,0.f,0.f);
    for (int g = 0; g < 4; g++) {
        const float ug = u[g];
        const float4* kvg = (const float4*)(kvs + g*1024);
        #pragma unroll 4
        for (int d = 0; d < 32; d++) {
            const float coef = ug * q[d];
            #pragma unroll
            for (int mq = 0; mq < 8; mq++) {
                float4 kvv = kvg[d*8 + mq];
                acc[mq].x += coef*kvv.x; acc[mq].y += coef*kvv.y;
                acc[mq].z += coef*kvv.z; acc[mq].w += coef*kvv.w;
            }
        }
    }
    const int b = bh >> 3, h = bh & 7;
    float4* op = (float4*)(g_attn + ((size_t)b*NN + n)*CC + h*HD);
    #pragma unroll
    for (int mq = 0; mq < 8; mq++) {
        acc[mq].x *= inv; acc[mq].y *= inv; acc[mq].z *= inv; acc[mq].w *= inv;
        op[mq] = acc[mq];
    }
}

// ---------------- launch ----------------
#define SM_PROJ ((2*128*36 + 2*128*36)*4)
#define SM_CONV ((2*64*36  + 2*256*36)*4)

extern "C" void kernel_launch(void* const* d_in, const int* in_sizes, int n_in,
                              void* d_out, int out_size)
{
    const float *query=0,*ipw=0,*ipb=0,*srw=0,*srb=0,*ng=0,*nb=0,*outw=0,*outb=0,*sew1=0,*sew2=0;
    int nbig = 0, n256 = 0, n32k = 0;
    for (int i = 0; i < n_in; i++) {
        const int s = in_sizes[i];
        const float* p = (const float*)d_in[i];
        if (s == 16777216)      { if (nbig++ == 0) query = p; }
        else if (s == 196608)   ipw = p;
        else if (s == 768)      ipb = p;
        else if (s == 262144)   srw = p;
        else if (s == 65536)    outw = p;
        else if (s == 32768)    { if (n32k++ == 0) sew1 = p; else sew2 = p; }
        else if (s == 256) {
            switch (n256++) {
                case 0: srb = p; break;
                case 1: ng  = p; break;
                case 2: nb  = p; break;
                case 3: outb= p; break;
            }
        }
    }
    float* out = (float*)d_out;

    cudaFuncSetAttribute(mm_tc<3,4,0,64,256,1024,8>,  cudaFuncAttributeMaxDynamicSharedMemorySize, SM_CONV);
    cudaFuncSetAttribute(mm_tc<0,2,0,128,128,256,10>, cudaFuncAttributeMaxDynamicSharedMemorySize, SM_PROJ);
    cudaFuncSetAttribute(mm_tc<1,0,1,128,128,256,8>,  cudaFuncAttributeMaxDynamicSharedMemorySize, SM_PROJ);
    cudaFuncSetAttribute(mm_tc<1,1,2,128,128,256,8>,  cudaFuncAttributeMaxDynamicSharedMemorySize, SM_PROJ);
    cudaFuncSetAttribute(mm_tc<2,3,3,128,128,256,10>, cudaFuncAttributeMaxDynamicSharedMemorySize, SM_PROJ);

    prep_kernel<<<2048, 256>>>(ipw, outw, srw);
    se_kernel<<<BB, 256>>>(query, sew1, sew2);
    // conv + LN  (M=16384 rows of 64)
    mm_tc<3,4,0,64,256,1024,8><<<256, 256, SM_CONV>>>(query, srb, ng, nb, nullptr);
    // q proj (M=65536)
    mm_tc<0,2,0,128,128,256,10><<<dim3(512,2), 256, SM_PROJ>>>(query, ipb, nullptr, nullptr, nullptr);
    // k proj (M=16384)
    mm_tc<1,0,1,128,128,256,8><<<dim3(128,2), 256, SM_PROJ>>>(nullptr, ipb + CC, nullptr, nullptr, nullptr);
    // v proj
    mm_tc<1,1,2,128,128,256,8><<<dim3(128,2), 256, SM_PROJ>>>(nullptr, ipb + 2*CC, nullptr, nullptr, nullptr);
    kv_kernel<<<NBH, 256>>>();
    attn_kernel<<<dim3(4, NBH), 256>>>();
    // out proj (M=65536)
    mm_tc<2,3,3,128,128,256,10><<<dim3(512,2), 256, SM_PROJ>>>(nullptr, outb, nullptr, nullptr, out);
    (void)out_size;
}

// round 9
// speedup vs baseline: 1.6378x; 1.0891x over previous
#include <cuda_runtime.h>
#include <math.h>
#include <stdint.h>

#define BB 64
#define NN 1024
#define CC 256
#define NSAMP 256
#define NH 8
#define HD 32
#define NBH (BB*NH)

__device__ float g_xr[BB*NSAMP*CC];
__device__ float g_q[NBH*NN*HD];
__device__ float g_k[NBH*NSAMP*HD];
__device__ float g_v[NBH*NSAMP*HD];
__device__ float g_kv[NBH*4*HD*HD];
__device__ float g_ksum[NBH*4*HD];
__device__ float g_attn[BB*NN*CC];
__device__ float g_se[BB*CC];
__device__ float g_wc_hi[256*1024];
__device__ float g_wc_lo[256*1024];
__device__ float g_wp_hi[4*256*256];
__device__ float g_wp_lo[4*256*256];

__device__ __forceinline__ void split_tf32(float a, float& hi, float& lo) {
    uint32_t u;
    asm("cvt.rna.tf32.f32 %0, %1;" : "=r"(u) : "f"(a));
    hi = __uint_as_float(u);
    lo = a - hi;
}

__device__ __forceinline__ void mma8(float* d, const float* a, const float* b) {
    asm volatile(
        "mma.sync.aligned.m16n8k8.row.col.f32.tf32.tf32.f32 "
        "{%0,%1,%2,%3}, {%4,%5,%6,%7}, {%8,%9}, {%0,%1,%2,%3};"
        : "+f"(d[0]), "+f"(d[1]), "+f"(d[2]), "+f"(d[3])
        : "r"(__float_as_uint(a[0])), "r"(__float_as_uint(a[1])),
          "r"(__float_as_uint(a[2])), "r"(__float_as_uint(a[3])),
          "r"(__float_as_uint(b[0])), "r"(__float_as_uint(b[1])));
}

// ---------------- weight prep: reorder + hi/lo split ----------------
__global__ __launch_bounds__(256) void prep_kernel(
    const float* __restrict__ ipw, const float* __restrict__ outw,
    const float* __restrict__ srw)
{
    int idx = blockIdx.x*256 + threadIdx.x;
    if (idx < 262144) {
        int oc = idx >> 10, k = idx & 1023, p = k >> 8, ci = k & 255;
        float v = srw[oc*1024 + ci*4 + p];
        float h, l; split_tf32(v, h, l);
        g_wc_hi[idx] = h; g_wc_lo[idx] = l;
    } else {
        int j = idx - 262144;
        int m = j >> 16;
        const float* src = (m < 3) ? (ipw + m*65536) : outw;
        float v = src[j & 65535];
        float h, l; split_tf32(v, h, l);
        g_wp_hi[j] = h; g_wp_lo[j] = l;
    }
}

// ---------------- SE ----------------
__global__ __launch_bounds__(256) void se_kernel(
    const float* __restrict__ query, const float* __restrict__ w1,
    const float* __restrict__ w2)
{
    const int b = blockIdx.x, c = threadIdx.x;
    const float* p = query + (size_t)b*CC + c;
    float a0=0.f,a1=0.f,a2=0.f,a3=0.f;
    for (int n = 0; n < NN; n += 4) {
        a0 += p[(size_t)(n+0)*(BB*CC)];
        a1 += p[(size_t)(n+1)*(BB*CC)];
        a2 += p[(size_t)(n+2)*(BB*CC)];
        a3 += p[(size_t)(n+3)*(BB*CC)];
    }
    __shared__ float sm[CC];
    __shared__ float s1[CC/2];
    sm[c] = (a0+a1+a2+a3) * (1.0f/NN);
    __syncthreads();
    if (c < 128) {
        float r = 0.f;
        const float* wr = w1 + (size_t)c*CC;
        #pragma unroll 8
        for (int i = 0; i < CC; i++) r += sm[i]*wr[i];
        s1[c] = fmaxf(r, 0.f);
    }
    __syncthreads();
    {
        float r = 0.f;
        const float* wr = w2 + (size_t)c*128;
        #pragma unroll 8
        for (int j = 0; j < 128; j++) r += s1[j]*wr[j];
        g_se[b*CC + c] = 1.0f / (1.0f + expf(-r));
    }
}

// =======================================================================
// mma.sync tf32 GEMM, 3-term hi/lo split.
// ASRC: 0=query gather (row=b*1024+n), 1=g_xr, 2=g_attn, 3=conv gather
// EMODE: 2=q(scale+relu,split-head) 3=out(SE gate scatter)
//        4=conv(bias+LayerNorm -> g_xr) 5=fused k+v (ncol0 selects)
// =======================================================================
template<int ASRC, int EMODE, int WSEL, int MTILE, int NTOT, int KTOT, int LB>
__global__ __launch_bounds__(256, 2) void mm_tc(
    const float* __restrict__ Ain, const float* __restrict__ bias,
    const float* __restrict__ aux0, const float* __restrict__ aux1,
    float* __restrict__ outp)
{
    constexpr int WM = MTILE/32;        // warps along M
    constexpr int LROWS = 1<<LB;
    extern __shared__ float smf[];
    float* sAhi = smf;
    float* sAlo = smf + MTILE*36;
    float* sWhi = smf + 2*MTILE*36;
    float* sWlo = smf + 2*MTILE*36 + NTOT*36;

    const int t = threadIdx.x, lane = t & 31, wid = t >> 5;
    const int g = lane >> 2, t4 = lane & 3;
    const int warp_m = wid & (WM-1);
    const int warp_n = wid / WM;
    const int ncol0 = blockIdx.y * NTOT;
    const int grow0 = blockIdx.x * MTILE;

    const float* Whi_src = (ASRC==3) ? g_wc_hi : (g_wp_hi + WSEL*65536);
    const float* Wlo_src = (ASRC==3) ? g_wc_lo : (g_wp_lo + WSEL*65536);

    float acc[2][8][4];
    #pragma unroll
    for (int mt=0; mt<2; mt++)
        #pragma unroll
        for (int nt=0; nt<8; nt++)
            #pragma unroll
            for (int q=0; q<4; q++) acc[mt][nt][q] = 0.f;

    constexpr int NCH = KTOT/32;
    for (int c = 0; c < NCH; c++) {
        // ---- stage A (hi/lo on the fly) ----
        #pragma unroll
        for (int i = 0; i < MTILE/32; i++) {
            int idx = t + i*256;
            int row = idx >> 3, q4 = idx & 7;
            int r = grow0 + row;
            const float* p;
            if (ASRC == 3) {
                int b = r >> 8, ns = r & 255;
                int py = (ns >> 4)*2, px = (ns & 15)*2;
                int pp = c >> 3, ci0 = (c & 7)*32;
                int pix = (py + (pp>>1))*32 + px + (pp&1);
                p = Ain + (size_t)pix*(BB*CC) + b*CC + ci0 + q4*4;
            } else if (ASRC == 0) {
                p = Ain + (size_t)(r & (LROWS-1))*(BB*CC) + (r>>LB)*CC + c*32 + q4*4;
            } else {
                const float* base = (ASRC==1) ? g_xr : g_attn;
                p = base + (size_t)r*CC + c*32 + q4*4;
            }
            float4 v = *(const float4*)p;
            float h0,h1,h2,h3,l0,l1,l2,l3;
            split_tf32(v.x,h0,l0); split_tf32(v.y,h1,l1);
            split_tf32(v.z,h2,l2); split_tf32(v.w,h3,l3);
            int off = row*36 + q4*4;
            *(float4*)(sAhi+off) = make_float4(h0,h1,h2,h3);
            *(float4*)(sAlo+off) = make_float4(l0,l1,l2,l3);
        }
        // ---- stage W (pre-split) ----
        #pragma unroll
        for (int i = 0; i < NTOT/32; i++) {
            int idx = t + i*256;
            int row = idx >> 3, q4 = idx & 7;
            size_t go = (size_t)(ncol0 + row)*KTOT + c*32 + q4*4;
            int off = row*36 + q4*4;
            *(float4*)(sWhi+off) = *(const float4*)(Whi_src + go);
            *(float4*)(sWlo+off) = *(const float4*)(Wlo_src + go);
        }
        __syncthreads();
        // ---- 4 k-steps of 8 ----
        #pragma unroll
        for (int ks = 0; ks < 4; ks++) {
            const int k0 = ks*8;
            float ah[2][4], al[2][4];
            #pragma unroll
            for (int mt=0; mt<2; mt++) {
                int rb = (warp_m*32 + mt*16 + g)*36 + k0 + t4;
                ah[mt][0]=sAhi[rb];       ah[mt][1]=sAhi[rb+288];
                ah[mt][2]=sAhi[rb+4];     ah[mt][3]=sAhi[rb+292];
                al[mt][0]=sAlo[rb];       al[mt][1]=sAlo[rb+288];
                al[mt][2]=sAlo[rb+4];     al[mt][3]=sAlo[rb+292];
            }
            #pragma unroll
            for (int nt=0; nt<8; nt++) {
                int nb = (warp_n*64 + nt*8 + g)*36 + k0 + t4;
                float bh[2], bl[2];
                bh[0]=sWhi[nb]; bh[1]=sWhi[nb+4];
                bl[0]=sWlo[nb]; bl[1]=sWlo[nb+4];
                #pragma unroll
                for (int mt=0; mt<2; mt++) {
                    mma8(acc[mt][nt], ah[mt], bh);
                    mma8(acc[mt][nt], ah[mt], bl);
                    mma8(acc[mt][nt], al[mt], bh);
                }
            }
        }
        __syncthreads();
    }

    // ================= epilogues =================
    if (EMODE == 4) {
        __shared__ float lnp[64][4], lnq[64][4], lnmu[64], lniv[64];
        float ps[2][2] = {{0.f,0.f},{0.f,0.f}};
        float pq[2][2] = {{0.f,0.f},{0.f,0.f}};
        #pragma unroll
        for (int mt=0; mt<2; mt++)
            #pragma unroll
            for (int nt=0; nt<8; nt++) {
                int gcol = warp_n*64 + nt*8 + t4*2;
                float2 bb = *(const float2*)(bias + gcol);
                float v0=acc[mt][nt][0]+bb.x, v1=acc[mt][nt][1]+bb.y;
                float v2=acc[mt][nt][2]+bb.x, v3=acc[mt][nt][3]+bb.y;
                acc[mt][nt][0]=v0; acc[mt][nt][1]=v1;
                acc[mt][nt][2]=v2; acc[mt][nt][3]=v3;
                ps[mt][0]+=v0+v1; pq[mt][0]+=v0*v0+v1*v1;
                ps[mt][1]+=v2+v3; pq[mt][1]+=v2*v2+v3*v3;
            }
        #pragma unroll
        for (int mt=0; mt<2; mt++)
            #pragma unroll
            for (int hf=0; hf<2; hf++) {
                float s = ps[mt][hf], q = pq[mt][hf];
                s += __shfl_xor_sync(0xffffffffu, s, 1);
                s += __shfl_xor_sync(0xffffffffu, s, 2);
                q += __shfl_xor_sync(0xffffffffu, q, 1);
                q += __shfl_xor_sync(0xffffffffu, q, 2);
                if (t4 == 0) {
                    int row = warp_m*32 + mt*16 + g + hf*8;
                    lnp[row][warp_n] = s; lnq[row][warp_n] = q;
                }
            }
        __syncthreads();
        if (t < 64) {
            float s = lnp[t][0]+lnp[t][1]+lnp[t][2]+lnp[t][3];
            float q = lnq[t][0]+lnq[t][1]+lnq[t][2]+lnq[t][3];
            float mu = s*(1.f/256.f);
            lnmu[t] = mu;
            lniv[t] = rsqrtf(q*(1.f/256.f) - mu*mu + 1e-5f);
        }
        __syncthreads();
        #pragma unroll
        for (int mt=0; mt<2; mt++) {
            int ra = warp_m*32 + mt*16 + g;
            float mua = lnmu[ra],   iva = lniv[ra];
            float mub = lnmu[ra+8], ivb = lniv[ra+8];
            #pragma unroll
            for (int nt=0; nt<8; nt++) {
                int gcol = warp_n*64 + nt*8 + t4*2;
                float2 gv = *(const float2*)(aux0 + gcol);
                float2 bv = *(const float2*)(aux1 + gcol);
                float o0 = (acc[mt][nt][0]-mua)*iva*gv.x + bv.x;
                float o1 = (acc[mt][nt][1]-mua)*iva*gv.y + bv.y;
                float o2 = (acc[mt][nt][2]-mub)*ivb*gv.x + bv.x;
                float o3 = (acc[mt][nt][3]-mub)*ivb*gv.y + bv.y;
                *(float2*)(g_xr + (size_t)(grow0+ra)*CC + gcol)   = make_float2(o0,o1);
                *(float2*)(g_xr + (size_t)(grow0+ra+8)*CC + gcol) = make_float2(o2,o3);
            }
        }
    } else {
        const bool isv = (EMODE == 5) && (ncol0 >= 256);
        #pragma unroll
        for (int mt=0; mt<2; mt++) {
            int r1 = grow0 + warp_m*32 + mt*16 + g;
            int b1 = r1 >> LB;
            int n1 = r1 & (LROWS-1);
            int n2 = n1 + 8;
            #pragma unroll
            for (int nt=0; nt<8; nt++) {
                int gcol = ncol0 + warp_n*64 + nt*8 + t4*2;
                float2 bb = *(const float2*)(bias + gcol);
                float v0=acc[mt][nt][0]+bb.x, v1=acc[mt][nt][1]+bb.y;
                float v2=acc[mt][nt][2]+bb.x, v3=acc[mt][nt][3]+bb.y;
                if (EMODE == 2) {
                    const float sc = 0.17677669529663687f;
                    v0=fmaxf(v0*sc,0.f); v1=fmaxf(v1*sc,0.f);
                    v2=fmaxf(v2*sc,0.f); v3=fmaxf(v3*sc,0.f);
                }
                if (EMODE == 5 && !isv) {
                    v0=fmaxf(v0,0.f); v1=fmaxf(v1,0.f);
                    v2=fmaxf(v2,0.f); v3=fmaxf(v3,0.f);
                }
                if (EMODE == 3) {
                    float2 se = *(const float2*)(g_se + b1*CC + gcol);
                    *(float2*)(outp + ((size_t)n1*BB + b1)*CC + gcol) = make_float2(v0*se.x, v1*se.y);
                    *(float2*)(outp + ((size_t)n2*BB + b1)*CC + gcol) = make_float2(v2*se.x, v3*se.y);
                } else {
                    int hcol = gcol & 255;
                    int h = hcol >> 5, d = hcol & 31;
                    float* gb = (EMODE==2) ? g_q : (isv ? g_v : g_k);
                    size_t base = ((size_t)(b1*NH + h) << LB);
                    *(float2*)(gb + (base + n1)*HD + d) = make_float2(v0,v1);
                    *(float2*)(gb + (base + n2)*HD + d) = make_float2(v2,v3);
                }
            }
        }
    }
}

// ---------------- kv accumulation ----------------
__global__ __launch_bounds__(256) void kv_kernel()
{
    const int bh = blockIdx.x;
    const int t  = threadIdx.x;
    const int m  = t & 31, dq = t >> 5;
    __shared__ __align__(16) float ks[128*32];
    __shared__ __align__(16) float vs[128*32];
    __shared__ float wsm[4][128];
    float acc[4][4];
    #pragma unroll
    for (int g = 0; g < 4; g++)
        #pragma unroll
        for (int di = 0; di < 4; di++) acc[g][di] = 0.f;
    float ksacc = 0.f;

    for (int half = 0; half < 2; half++) {
        __syncthreads();
        const float4* kp = (const float4*)(g_k + ((size_t)bh*NSAMP + half*128)*HD);
        const float4* vp = (const float4*)(g_v + ((size_t)bh*NSAMP + half*128)*HD);
        float4* ks4 = (float4*)ks;
        float4* vs4 = (float4*)vs;
        #pragma unroll
        for (int i = 0; i < 4; i++) {
            ks4[t + i*256] = kp[t + i*256];
            vs4[t + i*256] = vp[t + i*256];
        }
        if (t < 128) {
            const int ns = half*128 + t;
            const float aa = 1.57079632679489662f * (float)(ns >> 4) * (1.f/16.f);
            const float ab = 1.57079632679489662f * (float)(ns & 15) * (1.f/16.f);
            wsm[0][t] = cosf(aa); wsm[1][t] = sinf(aa);
            wsm[2][t] = cosf(ab); wsm[3][t] = sinf(ab);
        }
        __syncthreads();
        #pragma unroll 4
        for (int nl = 0; nl < 128; nl++) {
            const float wv = vs[nl*32 + m];
            float4 kd = *(const float4*)&ks[nl*32 + dq*4];
            float w0 = wsm[0][nl]*wv, w1 = wsm[1][nl]*wv;
            float w2 = wsm[2][nl]*wv, w3 = wsm[3][nl]*wv;
            acc[0][0]+=kd.x*w0; acc[0][1]+=kd.y*w0; acc[0][2]+=kd.z*w0; acc[0][3]+=kd.w*w0;
            acc[1][0]+=kd.x*w1; acc[1][1]+=kd.y*w1; acc[1][2]+=kd.z*w1; acc[1][3]+=kd.w*w1;
            acc[2][0]+=kd.x*w2; acc[2][1]+=kd.y*w2; acc[2][2]+=kd.z*w2; acc[2][3]+=kd.w*w2;
            acc[3][0]+=kd.x*w3; acc[3][1]+=kd.y*w3; acc[3][2]+=kd.z*w3; acc[3][3]+=kd.w*w3;
        }
        if (t < 128) {
            const int g = t >> 5, d = t & 31;
            float s = 0.f;
            #pragma unroll 8
            for (int nl = 0; nl < 128; nl++) s += wsm[g][nl] * ks[nl*32 + d];
            ksacc += s;
        }
    }
    float* kvp = g_kv + (size_t)bh*4096;
    #pragma unroll
    for (int g = 0; g < 4; g++)
        #pragma unroll
        for (int di = 0; di < 4; di++)
            kvp[(g*32 + dq*4 + di)*32 + m] = acc[g][di];
    if (t < 128) g_ksum[bh*128 + t] = ksacc;
}

// ---------------- per-query attention: 4 queries x 8 m-cols per thread ----------------
__global__ __launch_bounds__(256) void attn_kernel()
{
    const int bh = blockIdx.y;          // 512
    const int mc = blockIdx.x;          // 0..3 (8-col m chunk)
    const int t  = threadIdx.x;         // query within quarter
    __shared__ __align__(16) float kvs[4][32][8];   // 4KB, this block's m chunk
    __shared__ float ksums[128];
    {
        const float* kvp = g_kv + (size_t)bh*4096 + mc*8;
        for (int i = t; i < 1024; i += 256) {
            int gg = i >> 8, rem = i & 255, d = rem >> 3, m = rem & 7;
            kvs[gg][d][m] = kvp[(gg*32 + d)*32 + m];
        }
        if (t < 128) ksums[t] = g_ksum[bh*128 + t];
    }
    __syncthreads();

    // load 4 query rows: n_j = j*256 + t
    float qv[4][32];
    float u[4][4];
    #pragma unroll
    for (int j = 0; j < 4; j++) {
        const int n = j*256 + t;
        const float4* qp = (const float4*)(g_q + ((size_t)bh*NN + n)*HD);
        #pragma unroll
        for (int i = 0; i < 8; i++) {
            float4 v = qp[i];
            qv[j][i*4+0]=v.x; qv[j][i*4+1]=v.y; qv[j][i*4+2]=v.z; qv[j][i*4+3]=v.w;
        }
        const float aa = 1.57079632679489662f * (float)(n >> 5) * (1.f/32.f);
        const float ab = 1.57079632679489662f * (float)(n & 31) * (1.f/32.f);
        u[j][0]=cosf(aa); u[j][1]=sinf(aa); u[j][2]=cosf(ab); u[j][3]=sinf(ab);
    }

    // denominators
    float inv[4];
    #pragma unroll
    for (int j = 0; j < 4; j++) {
        float den = 0.f;
        #pragma unroll
        for (int gg = 0; gg < 4; gg++) {
            float s = 0.f;
            #pragma unroll
            for (int d = 0; d < 32; d++) s += qv[j][d]*ksums[gg*32+d];
            den += u[j][gg]*s;
        }
        float ad = fminf(fmaxf(fabsf(den), 1e-4f), 1e4f);
        inv[j] = 1.0f / copysignf(ad, den);
    }

    float acc[4][8];
    #pragma unroll
    for (int j = 0; j < 4; j++)
        #pragma unroll
        for (int m = 0; m < 8; m++) acc[j][m] = 0.f;

    #pragma unroll 1
    for (int gg = 0; gg < 4; gg++) {
        #pragma unroll
        for (int d = 0; d < 32; d++) {
            float4 k0 = *(const float4*)&kvs[gg][d][0];
            float4 k1 = *(const float4*)&kvs[gg][d][4];
            #pragma unroll
            for (int j = 0; j < 4; j++) {
                const float coef = u[j][gg] * qv[j][d];
                acc[j][0] += coef*k0.x; acc[j][1] += coef*k0.y;
                acc[j][2] += coef*k0.z; acc[j][3] += coef*k0.w;
                acc[j][4] += coef*k1.x; acc[j][5] += coef*k1.y;
                acc[j][6] += coef*k1.z; acc[j][7] += coef*k1.w;
            }
        }
    }

    const int b = bh >> 3, h = bh & 7;
    #pragma unroll
    for (int j = 0; j < 4; j++) {
        const int n = j*256 + t;
        float4* op = (float4*)(g_attn + ((size_t)b*NN + n)*CC + h*HD + mc*8);
        op[0] = make_float4(acc[j][0]*inv[j], acc[j][1]*inv[j],
                            acc[j][2]*inv[j], acc[j][3]*inv[j]);
        op[1] = make_float4(acc[j][4]*inv[j], acc[j][5]*inv[j],
                            acc[j][6]*inv[j], acc[j][7]*inv[j]);
    }
}

// ---------------- launch ----------------
#define SM_PROJ ((2*128*36 + 2*128*36)*4)
#define SM_CONV ((2*64*36  + 2*256*36)*4)

extern "C" void kernel_launch(void* const* d_in, const int* in_sizes, int n_in,
                              void* d_out, int out_size)
{
    const float *query=0,*ipw=0,*ipb=0,*srw=0,*srb=0,*ng=0,*nb=0,*outw=0,*outb=0,*sew1=0,*sew2=0;
    int nbig = 0, n256 = 0, n32k = 0;
    for (int i = 0; i < n_in; i++) {
        const int s = in_sizes[i];
        const float* p = (const float*)d_in[i];
        if (s == 16777216)      { if (nbig++ == 0) query = p; }
        else if (s == 196608)   ipw = p;
        else if (s == 768)      ipb = p;
        else if (s == 262144)   srw = p;
        else if (s == 65536)    outw = p;
        else if (s == 32768)    { if (n32k++ == 0) sew1 = p; else sew2 = p; }
        else if (s == 256) {
            switch (n256++) {
                case 0: srb = p; break;
                case 1: ng  = p; break;
                case 2: nb  = p; break;
                case 3: outb= p; break;
            }
        }
    }
    float* out = (float*)d_out;

    cudaFuncSetAttribute(mm_tc<3,4,0,64,256,1024,8>,  cudaFuncAttributeMaxDynamicSharedMemorySize, SM_CONV);
    cudaFuncSetAttribute(mm_tc<0,2,0,128,128,256,10>, cudaFuncAttributeMaxDynamicSharedMemorySize, SM_PROJ);
    cudaFuncSetAttribute(mm_tc<1,5,1,128,128,256,8>,  cudaFuncAttributeMaxDynamicSharedMemorySize, SM_PROJ);
    cudaFuncSetAttribute(mm_tc<2,3,3,128,128,256,10>, cudaFuncAttributeMaxDynamicSharedMemorySize, SM_PROJ);

    prep_kernel<<<2048, 256>>>(ipw, outw, srw);
    se_kernel<<<BB, 256>>>(query, sew1, sew2);
    // conv + LN  (M=16384 rows of 64)
    mm_tc<3,4,0,64,256,1024,8><<<256, 256, SM_CONV>>>(query, srb, ng, nb, nullptr);
    // q proj (M=65536)
    mm_tc<0,2,0,128,128,256,10><<<dim3(512,2), 256, SM_PROJ>>>(query, ipb, nullptr, nullptr, nullptr);
    // fused k+v proj (M=16384, N=512)
    mm_tc<1,5,1,128,128,256,8><<<dim3(128,4), 256, SM_PROJ>>>(nullptr, ipb + CC, nullptr, nullptr, nullptr);
    kv_kernel<<<NBH, 256>>>();
    attn_kernel<<<dim3(4, NBH), 256>>>();
    // out proj (M=65536)
    mm_tc<2,3,3,128,128,256,10><<<dim3(512,2), 256, SM_PROJ>>>(nullptr, outb, nullptr, nullptr, out);
    (void)out_size;
}

// round 10
// speedup vs baseline: 1.6683x; 1.0187x over previous
#include <cuda_runtime.h>
#include <math.h>
#include <stdint.h>

#define BB 64
#define NN 1024
#define CC 256
#define NSAMP 256
#define NH 8
#define HD 32
#define NBH (BB*NH)

__device__ float g_xr[BB*NSAMP*CC];
__device__ float g_q[NBH*NN*HD];
__device__ float g_k[NBH*NSAMP*HD];
__device__ float g_v[NBH*NSAMP*HD];
__device__ float g_kv[NBH*4*HD*HD];
__device__ float g_ksum[NBH*4*HD];
__device__ float g_attn[BB*NN*CC];
__device__ float g_se[BB*CC];
__device__ float g_wc_hi[256*1024];
__device__ float g_wc_lo[256*1024];
__device__ float g_wp_hi[4*256*256];
__device__ float g_wp_lo[4*256*256];

__device__ __forceinline__ void split_tf32(float a, float& hi, float& lo) {
    uint32_t u;
    asm("cvt.rna.tf32.f32 %0, %1;" : "=r"(u) : "f"(a));
    hi = __uint_as_float(u);
    lo = a - hi;
}

__device__ __forceinline__ void mma8(float* d, const float* a, const float* b) {
    asm("mma.sync.aligned.m16n8k8.row.col.f32.tf32.tf32.f32 "
        "{%0,%1,%2,%3}, {%4,%5,%6,%7}, {%8,%9}, {%0,%1,%2,%3};"
        : "+f"(d[0]), "+f"(d[1]), "+f"(d[2]), "+f"(d[3])
        : "r"(__float_as_uint(a[0])), "r"(__float_as_uint(a[1])),
          "r"(__float_as_uint(a[2])), "r"(__float_as_uint(a[3])),
          "r"(__float_as_uint(b[0])), "r"(__float_as_uint(b[1])));
}

__device__ __forceinline__ void cp16(float* sm, const float* gm) {
    uint32_t a = (uint32_t)__cvta_generic_to_shared(sm);
    asm volatile("cp.async.cg.shared.global [%0], [%1], 16;" :: "r"(a), "l"(gm) : "memory");
}
#define CP_COMMIT() asm volatile("cp.async.commit_group;" ::: "memory")
#define CP_WAIT(n)  asm volatile("cp.async.wait_group %0;" :: "n"(n) : "memory")

// ---------------- weight prep: reorder + hi/lo split ----------------
__global__ __launch_bounds__(256) void prep_kernel(
    const float* __restrict__ ipw, const float* __restrict__ outw,
    const float* __restrict__ srw)
{
    int idx = blockIdx.x*256 + threadIdx.x;
    if (idx < 262144) {
        int oc = idx >> 10, k = idx & 1023, p = k >> 8, ci = k & 255;
        float v = srw[oc*1024 + ci*4 + p];
        float h, l; split_tf32(v, h, l);
        g_wc_hi[idx] = h; g_wc_lo[idx] = l;
    } else {
        int j = idx - 262144;
        int m = j >> 16;
        const float* src = (m < 3) ? (ipw + m*65536) : outw;
        float v = src[j & 65535];
        float h, l; split_tf32(v, h, l);
        g_wp_hi[j] = h; g_wp_lo[j] = l;
    }
}

// ---------------- SE ----------------
__global__ __launch_bounds__(256) void se_kernel(
    const float* __restrict__ query, const float* __restrict__ w1,
    const float* __restrict__ w2)
{
    const int b = blockIdx.x, c = threadIdx.x;
    const float* p = query + (size_t)b*CC + c;
    float a0=0.f,a1=0.f,a2=0.f,a3=0.f;
    for (int n = 0; n < NN; n += 4) {
        a0 += p[(size_t)(n+0)*(BB*CC)];
        a1 += p[(size_t)(n+1)*(BB*CC)];
        a2 += p[(size_t)(n+2)*(BB*CC)];
        a3 += p[(size_t)(n+3)*(BB*CC)];
    }
    __shared__ float sm[CC];
    __shared__ float s1[CC/2];
    sm[c] = (a0+a1+a2+a3) * (1.0f/NN);
    __syncthreads();
    if (c < 128) {
        float r = 0.f;
        const float* wr = w1 + (size_t)c*CC;
        #pragma unroll 8
        for (int i = 0; i < CC; i++) r += sm[i]*wr[i];
        s1[c] = fmaxf(r, 0.f);
    }
    __syncthreads();
    {
        float r = 0.f;
        const float* wr = w2 + (size_t)c*128;
        #pragma unroll 8
        for (int j = 0; j < 128; j++) r += s1[j]*wr[j];
        g_se[b*CC + c] = 1.0f / (1.0f + expf(-r));
    }
}

// =======================================================================
// mma.sync tf32 GEMM, 3-term hi/lo split, cp.async 2-stage pipeline.
// A staged RAW in smem; hi/lo split happens at fragment load.
// ASRC: 0=query gather, 1=g_xr, 2=g_attn, 3=conv gather
// EMODE: 2=q(scale+relu,split-head) 3=out(SE gate scatter)
//        4=conv(bias+LayerNorm -> g_xr) 5=fused k+v (ncol0 selects)
// =======================================================================
template<int ASRC, int EMODE, int WSEL, int MTILE, int NTOT, int KTOT, int LB>
__global__ __launch_bounds__(256, 2) void mm_tc(
    const float* __restrict__ Ain, const float* __restrict__ bias,
    const float* __restrict__ aux0, const float* __restrict__ aux1,
    float* __restrict__ outp)
{
    constexpr int WM = MTILE/32;        // warps along M
    constexpr int LROWS = 1<<LB;
    constexpr int ASTR = MTILE*36;
    constexpr int WSTR = NTOT*36;
    constexpr int STG  = ASTR + 2*WSTR;
    extern __shared__ float smf[];

    const int t = threadIdx.x, lane = t & 31, wid = t >> 5;
    const int g = lane >> 2, t4 = lane & 3;
    const int warp_m = wid & (WM-1);
    const int warp_n = wid / WM;
    const int ncol0 = blockIdx.y * NTOT;
    const int grow0 = blockIdx.x * MTILE;

    const float* Whi_src = (ASRC==3) ? g_wc_hi : (g_wp_hi + WSEL*65536);
    const float* Wlo_src = (ASRC==3) ? g_wc_lo : (g_wp_lo + WSEL*65536);

    auto stage = [&](int c, int s) {
        float* sA  = smf + s*STG;
        float* sWh = sA + ASTR;
        float* sWl = sWh + WSTR;
        #pragma unroll
        for (int i = 0; i < MTILE/32; i++) {
            int idx = t + i*256;
            int row = idx >> 3, q4 = idx & 7;
            int r = grow0 + row;
            const float* p;
            if (ASRC == 3) {
                int b = r >> 8, ns = r & 255;
                int py = (ns >> 4)*2, px = (ns & 15)*2;
                int pp = c >> 3, ci0 = (c & 7)*32;
                int pix = (py + (pp>>1))*32 + px + (pp&1);
                p = Ain + (size_t)pix*(BB*CC) + b*CC + ci0 + q4*4;
            } else if (ASRC == 0) {
                p = Ain + (size_t)(r & (LROWS-1))*(BB*CC) + (r>>LB)*CC + c*32 + q4*4;
            } else {
                const float* base = (ASRC==1) ? g_xr : g_attn;
                p = base + (size_t)r*CC + c*32 + q4*4;
            }
            cp16(sA + row*36 + q4*4, p);
        }
        #pragma unroll
        for (int i = 0; i < NTOT/32; i++) {
            int idx = t + i*256;
            int row = idx >> 3, q4 = idx & 7;
            size_t go = (size_t)(ncol0 + row)*KTOT + c*32 + q4*4;
            int off = row*36 + q4*4;
            cp16(sWh + off, Whi_src + go);
            cp16(sWl + off, Wlo_src + go);
        }
        CP_COMMIT();
    };

    float acc[2][8][4];
    #pragma unroll
    for (int mt=0; mt<2; mt++)
        #pragma unroll
        for (int nt=0; nt<8; nt++)
            #pragma unroll
            for (int q=0; q<4; q++) acc[mt][nt][q] = 0.f;

    constexpr int NCH = KTOT/32;
    stage(0, 0);
    stage(1, 1);

    for (int c = 0; c < NCH; c++) {
        if (c < NCH-1) { CP_WAIT(1); } else { CP_WAIT(0); }
        __syncthreads();
        const int s = c & 1;
        float* sA  = smf + s*STG;
        float* sWh = sA + ASTR;
        float* sWl = sWh + WSTR;
        #pragma unroll
        for (int ks = 0; ks < 4; ks++) {
            const int k0 = ks*8;
            float ah[2][4], al[2][4];
            #pragma unroll
            for (int mt=0; mt<2; mt++) {
                int rb = (warp_m*32 + mt*16 + g)*36 + k0 + t4;
                float r0 = sA[rb],   r1 = sA[rb+288];
                float r2 = sA[rb+4], r3 = sA[rb+292];
                split_tf32(r0, ah[mt][0], al[mt][0]);
                split_tf32(r1, ah[mt][1], al[mt][1]);
                split_tf32(r2, ah[mt][2], al[mt][2]);
                split_tf32(r3, ah[mt][3], al[mt][3]);
            }
            #pragma unroll
            for (int nt=0; nt<8; nt++) {
                int nb = (warp_n*64 + nt*8 + g)*36 + k0 + t4;
                float bh[2], bl[2];
                bh[0]=sWh[nb]; bh[1]=sWh[nb+4];
                bl[0]=sWl[nb]; bl[1]=sWl[nb+4];
                mma8(acc[0][nt], ah[0], bh);
                mma8(acc[1][nt], ah[1], bh);
                mma8(acc[0][nt], al[0], bh);
                mma8(acc[1][nt], al[1], bh);
                mma8(acc[0][nt], ah[0], bl);
                mma8(acc[1][nt], ah[1], bl);
            }
        }
        __syncthreads();
        if (c + 2 < NCH) stage(c+2, s);
    }

    // ================= epilogues =================
    if (EMODE == 4) {
        __shared__ float lnp[64][4], lnq[64][4], lnmu[64], lniv[64];
        float ps[2][2] = {{0.f,0.f},{0.f,0.f}};
        float pq[2][2] = {{0.f,0.f},{0.f,0.f}};
        #pragma unroll
        for (int mt=0; mt<2; mt++)
            #pragma unroll
            for (int nt=0; nt<8; nt++) {
                int gcol = warp_n*64 + nt*8 + t4*2;
                float2 bb = *(const float2*)(bias + gcol);
                float v0=acc[mt][nt][0]+bb.x, v1=acc[mt][nt][1]+bb.y;
                float v2=acc[mt][nt][2]+bb.x, v3=acc[mt][nt][3]+bb.y;
                acc[mt][nt][0]=v0; acc[mt][nt][1]=v1;
                acc[mt][nt][2]=v2; acc[mt][nt][3]=v3;
                ps[mt][0]+=v0+v1; pq[mt][0]+=v0*v0+v1*v1;
                ps[mt][1]+=v2+v3; pq[mt][1]+=v2*v2+v3*v3;
            }
        #pragma unroll
        for (int mt=0; mt<2; mt++)
            #pragma unroll
            for (int hf=0; hf<2; hf++) {
                float s = ps[mt][hf], q = pq[mt][hf];
                s += __shfl_xor_sync(0xffffffffu, s, 1);
                s += __shfl_xor_sync(0xffffffffu, s, 2);
                q += __shfl_xor_sync(0xffffffffu, q, 1);
                q += __shfl_xor_sync(0xffffffffu, q, 2);
                if (t4 == 0) {
                    int row = warp_m*32 + mt*16 + g + hf*8;
                    lnp[row][warp_n] = s; lnq[row][warp_n] = q;
                }
            }
        __syncthreads();
        if (t < 64) {
            float s = lnp[t][0]+lnp[t][1]+lnp[t][2]+lnp[t][3];
            float q = lnq[t][0]+lnq[t][1]+lnq[t][2]+lnq[t][3];
            float mu = s*(1.f/256.f);
            lnmu[t] = mu;
            lniv[t] = rsqrtf(q*(1.f/256.f) - mu*mu + 1e-5f);
        }
        __syncthreads();
        #pragma unroll
        for (int mt=0; mt<2; mt++) {
            int ra = warp_m*32 + mt*16 + g;
            float mua = lnmu[ra],   iva = lniv[ra];
            float mub = lnmu[ra+8], ivb = lniv[ra+8];
            #pragma unroll
            for (int nt=0; nt<8; nt++) {
                int gcol = warp_n*64 + nt*8 + t4*2;
                float2 gv = *(const float2*)(aux0 + gcol);
                float2 bv = *(const float2*)(aux1 + gcol);
                float o0 = (acc[mt][nt][0]-mua)*iva*gv.x + bv.x;
                float o1 = (acc[mt][nt][1]-mua)*iva*gv.y + bv.y;
                float o2 = (acc[mt][nt][2]-mub)*ivb*gv.x + bv.x;
                float o3 = (acc[mt][nt][3]-mub)*ivb*gv.y + bv.y;
                *(float2*)(g_xr + (size_t)(grow0+ra)*CC + gcol)   = make_float2(o0,o1);
                *(float2*)(g_xr + (size_t)(grow0+ra+8)*CC + gcol) = make_float2(o2,o3);
            }
        }
    } else {
        const bool isv = (EMODE == 5) && (ncol0 >= 256);
        #pragma unroll
        for (int mt=0; mt<2; mt++) {
            int r1 = grow0 + warp_m*32 + mt*16 + g;
            int b1 = r1 >> LB;
            int n1 = r1 & (LROWS-1);
            int n2 = n1 + 8;
            #pragma unroll
            for (int nt=0; nt<8; nt++) {
                int gcol = ncol0 + warp_n*64 + nt*8 + t4*2;
                float2 bb = *(const float2*)(bias + gcol);
                float v0=acc[mt][nt][0]+bb.x, v1=acc[mt][nt][1]+bb.y;
                float v2=acc[mt][nt][2]+bb.x, v3=acc[mt][nt][3]+bb.y;
                if (EMODE == 2) {
                    const float sc = 0.17677669529663687f;
                    v0=fmaxf(v0*sc,0.f); v1=fmaxf(v1*sc,0.f);
                    v2=fmaxf(v2*sc,0.f); v3=fmaxf(v3*sc,0.f);
                }
                if (EMODE == 5 && !isv) {
                    v0=fmaxf(v0,0.f); v1=fmaxf(v1,0.f);
                    v2=fmaxf(v2,0.f); v3=fmaxf(v3,0.f);
                }
                if (EMODE == 3) {
                    float2 se = *(const float2*)(g_se + b1*CC + gcol);
                    *(float2*)(outp + ((size_t)n1*BB + b1)*CC + gcol) = make_float2(v0*se.x, v1*se.y);
                    *(float2*)(outp + ((size_t)n2*BB + b1)*CC + gcol) = make_float2(v2*se.x, v3*se.y);
                } else {
                    int hcol = gcol & 255;
                    int h = hcol >> 5, d = hcol & 31;
                    float* gb = (EMODE==2) ? g_q : (isv ? g_v : g_k);
                    size_t base = ((size_t)(b1*NH + h) << LB);
                    *(float2*)(gb + (base + n1)*HD + d) = make_float2(v0,v1);
                    *(float2*)(gb + (base + n2)*HD + d) = make_float2(v2,v3);
                }
            }
        }
    }
}

// ---------------- kv accumulation ----------------
__global__ __launch_bounds__(256) void kv_kernel()
{
    const int bh = blockIdx.x;
    const int t  = threadIdx.x;
    const int m  = t & 31, dq = t >> 5;
    __shared__ __align__(16) float ks[128*32];
    __shared__ __align__(16) float vs[128*32];
    __shared__ float wsm[4][128];
    float acc[4][4];
    #pragma unroll
    for (int g = 0; g < 4; g++)
        #pragma unroll
        for (int di = 0; di < 4; di++) acc[g][di] = 0.f;
    float ksacc = 0.f;

    for (int half = 0; half < 2; half++) {
        __syncthreads();
        const float4* kp = (const float4*)(g_k + ((size_t)bh*NSAMP + half*128)*HD);
        const float4* vp = (const float4*)(g_v + ((size_t)bh*NSAMP + half*128)*HD);
        float4* ks4 = (float4*)ks;
        float4* vs4 = (float4*)vs;
        #pragma unroll
        for (int i = 0; i < 4; i++) {
            ks4[t + i*256] = kp[t + i*256];
            vs4[t + i*256] = vp[t + i*256];
        }
        if (t < 128) {
            const int ns = half*128 + t;
            const float aa = 1.57079632679489662f * (float)(ns >> 4) * (1.f/16.f);
            const float ab = 1.57079632679489662f * (float)(ns & 15) * (1.f/16.f);
            wsm[0][t] = cosf(aa); wsm[1][t] = sinf(aa);
            wsm[2][t] = cosf(ab); wsm[3][t] = sinf(ab);
        }
        __syncthreads();
        #pragma unroll 4
        for (int nl = 0; nl < 128; nl++) {
            const float wv = vs[nl*32 + m];
            float4 kd = *(const float4*)&ks[nl*32 + dq*4];
            float w0 = wsm[0][nl]*wv, w1 = wsm[1][nl]*wv;
            float w2 = wsm[2][nl]*wv, w3 = wsm[3][nl]*wv;
            acc[0][0]+=kd.x*w0; acc[0][1]+=kd.y*w0; acc[0][2]+=kd.z*w0; acc[0][3]+=kd.w*w0;
            acc[1][0]+=kd.x*w1; acc[1][1]+=kd.y*w1; acc[1][2]+=kd.z*w1; acc[1][3]+=kd.w*w1;
            acc[2][0]+=kd.x*w2; acc[2][1]+=kd.y*w2; acc[2][2]+=kd.z*w2; acc[2][3]+=kd.w*w2;
            acc[3][0]+=kd.x*w3; acc[3][1]+=kd.y*w3; acc[3][2]+=kd.z*w3; acc[3][3]+=kd.w*w3;
        }
        if (t < 128) {
            const int g = t >> 5, d = t & 31;
            float s = 0.f;
            #pragma unroll 8
            for (int nl = 0; nl < 128; nl++) s += wsm[g][nl] * ks[nl*32 + d];
            ksacc += s;
        }
    }
    float* kvp = g_kv + (size_t)bh*4096;
    #pragma unroll
    for (int g = 0; g < 4; g++)
        #pragma unroll
        for (int di = 0; di < 4; di++)
            kvp[(g*32 + dq*4 + di)*32 + m] = acc[g][di];
    if (t < 128) g_ksum[bh*128 + t] = ksacc;
}

// ---------------- per-query attention: 4 queries x 8 m-cols per thread ----------------
__global__ __launch_bounds__(256) void attn_kernel()
{
    const int bh = blockIdx.y;
    const int mc = blockIdx.x;
    const int t  = threadIdx.x;
    __shared__ __align__(16) float kvs[4][32][8];
    __shared__ float ksums[128];
    {
        const float* kvp = g_kv + (size_t)bh*4096 + mc*8;
        for (int i = t; i < 1024; i += 256) {
            int gg = i >> 8, rem = i & 255, d = rem >> 3, m = rem & 7;
            kvs[gg][d][m] = kvp[(gg*32 + d)*32 + m];
        }
        if (t < 128) ksums[t] = g_ksum[bh*128 + t];
    }
    __syncthreads();

    float qv[4][32];
    float u[4][4];
    #pragma unroll
    for (int j = 0; j < 4; j++) {
        const int n = j*256 + t;
        const float4* qp = (const float4*)(g_q + ((size_t)bh*NN + n)*HD);
        #pragma unroll
        for (int i = 0; i < 8; i++) {
            float4 v = qp[i];
            qv[j][i*4+0]=v.x; qv[j][i*4+1]=v.y; qv[j][i*4+2]=v.z; qv[j][i*4+3]=v.w;
        }
        const float aa = 1.57079632679489662f * (float)(n >> 5) * (1.f/32.f);
        const float ab = 1.57079632679489662f * (float)(n & 31) * (1.f/32.f);
        u[j][0]=cosf(aa); u[j][1]=sinf(aa); u[j][2]=cosf(ab); u[j][3]=sinf(ab);
    }

    float inv[4];
    #pragma unroll
    for (int j = 0; j < 4; j++) {
        float den = 0.f;
        #pragma unroll
        for (int gg = 0; gg < 4; gg++) {
            float s = 0.f;
            #pragma unroll
            for (int d = 0; d < 32; d++) s += qv[j][d]*ksums[gg*32+d];
            den += u[j][gg]*s;
        }
        float ad = fminf(fmaxf(fabsf(den), 1e-4f), 1e4f);
        inv[j] = 1.0f / copysignf(ad, den);
    }

    float acc[4][8];
    #pragma unroll
    for (int j = 0; j < 4; j++)
        #pragma unroll
        for (int m = 0; m < 8; m++) acc[j][m] = 0.f;

    #pragma unroll 1
    for (int gg = 0; gg < 4; gg++) {
        #pragma unroll
        for (int d = 0; d < 32; d++) {
            float4 k0 = *(const float4*)&kvs[gg][d][0];
            float4 k1 = *(const float4*)&kvs[gg][d][4];
            #pragma unroll
            for (int j = 0; j < 4; j++) {
                const float coef = u[j][gg] * qv[j][d];
                acc[j][0] += coef*k0.x; acc[j][1] += coef*k0.y;
                acc[j][2] += coef*k0.z; acc[j][3] += coef*k0.w;
                acc[j][4] += coef*k1.x; acc[j][5] += coef*k1.y;
                acc[j][6] += coef*k1.z; acc[j][7] += coef*k1.w;
            }
        }
    }

    const int b = bh >> 3, h = bh & 7;
    #pragma unroll
    for (int j = 0; j < 4; j++) {
        const int n = j*256 + t;
        float4* op = (float4*)(g_attn + ((size_t)b*NN + n)*CC + h*HD + mc*8);
        op[0] = make_float4(acc[j][0]*inv[j], acc[j][1]*inv[j],
                            acc[j][2]*inv[j], acc[j][3]*inv[j]);
        op[1] = make_float4(acc[j][4]*inv[j], acc[j][5]*inv[j],
                            acc[j][6]*inv[j], acc[j][7]*inv[j]);
    }
}

// ---------------- launch ----------------
#define SM_PROJ (2*(128*36 + 2*128*36)*4)
#define SM_CONV (2*(64*36  + 2*256*36)*4)

extern "C" void kernel_launch(void* const* d_in, const int* in_sizes, int n_in,
                              void* d_out, int out_size)
{
    const float *query=0,*ipw=0,*ipb=0,*srw=0,*srb=0,*ng=0,*nb=0,*outw=0,*outb=0,*sew1=0,*sew2=0;
    int nbig = 0, n256 = 0, n32k = 0;
    for (int i = 0; i < n_in; i++) {
        const int s = in_sizes[i];
        const float* p = (const float*)d_in[i];
        if (s == 16777216)      { if (nbig++ == 0) query = p; }
        else if (s == 196608)   ipw = p;
        else if (s == 768)      ipb = p;
        else if (s == 262144)   srw = p;
        else if (s == 65536)    outw = p;
        else if (s == 32768)    { if (n32k++ == 0) sew1 = p; else sew2 = p; }
        else if (s == 256) {
            switch (n256++) {
                case 0: srb = p; break;
                case 1: ng  = p; break;
                case 2: nb  = p; break;
                case 3: outb= p; break;
            }
        }
    }
    float* out = (float*)d_out;

    cudaFuncSetAttribute(mm_tc<3,4,0,64,256,1024,8>,  cudaFuncAttributeMaxDynamicSharedMemorySize, SM_CONV);
    cudaFuncSetAttribute(mm_tc<0,2,0,128,128,256,10>, cudaFuncAttributeMaxDynamicSharedMemorySize, SM_PROJ);
    cudaFuncSetAttribute(mm_tc<1,5,1,128,128,256,8>,  cudaFuncAttributeMaxDynamicSharedMemorySize, SM_PROJ);
    cudaFuncSetAttribute(mm_tc<2,3,3,128,128,256,10>, cudaFuncAttributeMaxDynamicSharedMemorySize, SM_PROJ);

    prep_kernel<<<2048, 256>>>(ipw, outw, srw);
    se_kernel<<<BB, 256>>>(query, sew1, sew2);
    // conv + LN  (M=16384 rows of 64)
    mm_tc<3,4,0,64,256,1024,8><<<256, 256, SM_CONV>>>(query, srb, ng, nb, nullptr);
    // q proj (M=65536)
    mm_tc<0,2,0,128,128,256,10><<<dim3(512,2), 256, SM_PROJ>>>(query, ipb, nullptr, nullptr, nullptr);
    // fused k+v proj (M=16384, N=512)
    mm_tc<1,5,1,128,128,256,8><<<dim3(128,4), 256, SM_PROJ>>>(nullptr, ipb + CC, nullptr, nullptr, nullptr);
    kv_kernel<<<NBH, 256>>>();
    attn_kernel<<<dim3(4, NBH), 256>>>();
    // out proj (M=65536)
    mm_tc<2,3,3,128,128,256,10><<<dim3(512,2), 256, SM_PROJ>>>(nullptr, outb, nullptr, nullptr, out);
    (void)out_size;
}

// round 12
// speedup vs baseline: 2.1968x; 1.3168x over previous
#include <cuda_runtime.h>
#include <cuda_bf16.h>
#include <math.h>
#include <stdint.h>

#define BB 64
#define NN 1024
#define CC 256
#define NSAMP 256
#define NH 8
#define HD 32
#define NBH (BB*NH)

__device__ float g_xr[BB*NSAMP*CC];
__device__ float g_q[NBH*NN*HD];
__device__ float g_k[NBH*NSAMP*HD];
__device__ float g_v[NBH*NSAMP*HD];
__device__ float g_kv[NBH*4*HD*HD];
__device__ float g_ksum[NBH*4*HD];
__device__ float g_attn[BB*NN*CC];
__device__ float g_se[BB*CC];
__device__ __nv_bfloat16 g_wc_hi[256*1024];
__device__ __nv_bfloat16 g_wc_lo[256*1024];
__device__ __nv_bfloat16 g_wp_hi[4*256*256];
__device__ __nv_bfloat16 g_wp_lo[4*256*256];

// split x,y into packed bf16 hi pair + bf16 residual pair (lo16 = first elem)
__device__ __forceinline__ void splitb(float x, float y, uint32_t& hi, uint32_t& lo) {
    uint32_t h; asm("cvt.rn.bf16x2.f32 %0, %1, %2;" : "=r"(h) : "f"(y), "f"(x));
    float hx = __uint_as_float(h << 16);
    float hy = __uint_as_float(h & 0xFFFF0000u);
    float rx = x - hx, ry = y - hy;
    uint32_t l; asm("cvt.rn.bf16x2.f32 %0, %1, %2;" : "=r"(l) : "f"(ry), "f"(rx));
    hi = h; lo = l;
}

__device__ __forceinline__ void mma16(float* d, const uint32_t* a, const uint32_t* b) {
    asm("mma.sync.aligned.m16n8k16.row.col.f32.bf16.bf16.f32 "
        "{%0,%1,%2,%3}, {%4,%5,%6,%7}, {%8,%9}, {%0,%1,%2,%3};"
        : "+f"(d[0]), "+f"(d[1]), "+f"(d[2]), "+f"(d[3])
        : "r"(a[0]), "r"(a[1]), "r"(a[2]), "r"(a[3]), "r"(b[0]), "r"(b[1]));
}

__device__ __forceinline__ void cp16(void* sm, const void* gm) {
    uint32_t a = (uint32_t)__cvta_generic_to_shared(sm);
    asm volatile("cp.async.cg.shared.global [%0], [%1], 16;" :: "r"(a), "l"(gm) : "memory");
}
#define CP_COMMIT() asm volatile("cp.async.commit_group;" ::: "memory")
#define CP_WAIT(n)  asm volatile("cp.async.wait_group %0;" :: "n"(n) : "memory")

// ---------------- weight prep: reorder + bf16 hi/lo split ----------------
__global__ __launch_bounds__(256) void prep_kernel(
    const float* __restrict__ ipw, const float* __restrict__ outw,
    const float* __restrict__ srw)
{
    int idx = blockIdx.x*256 + threadIdx.x;
    float v;
    __nv_bfloat16 *dh, *dl;
    if (idx < 262144) {
        int oc = idx >> 10, k = idx & 1023, p = k >> 8, ci = k & 255;
        v = srw[oc*1024 + ci*4 + p];
        dh = g_wc_hi + idx; dl = g_wc_lo + idx;
    } else {
        int j = idx - 262144;
        int m = j >> 16;
        const float* src = (m < 3) ? (ipw + m*65536) : outw;
        v = src[j & 65535];
        dh = g_wp_hi + j; dl = g_wp_lo + j;
    }
    __nv_bfloat16 h = __float2bfloat16(v);
    float hf = __uint_as_float(((uint32_t)__bfloat16_as_ushort(h)) << 16);
    *dh = h;
    *dl = __float2bfloat16(v - hf);
}

// ---------------- SE ----------------
__global__ __launch_bounds__(256) void se_kernel(
    const float* __restrict__ query, const float* __restrict__ w1,
    const float* __restrict__ w2)
{
    const int b = blockIdx.x, c = threadIdx.x;
    const float* p = query + (size_t)b*CC + c;
    float a0=0.f,a1=0.f,a2=0.f,a3=0.f;
    for (int n = 0; n < NN; n += 4) {
        a0 += p[(size_t)(n+0)*(BB*CC)];
        a1 += p[(size_t)(n+1)*(BB*CC)];
        a2 += p[(size_t)(n+2)*(BB*CC)];
        a3 += p[(size_t)(n+3)*(BB*CC)];
    }
    __shared__ float sm[CC];
    __shared__ float s1[CC/2];
    sm[c] = (a0+a1+a2+a3) * (1.0f/NN);
    __syncthreads();
    if (c < 128) {
        float r = 0.f;
        const float* wr = w1 + (size_t)c*CC;
        #pragma unroll 8
        for (int i = 0; i < CC; i++) r += sm[i]*wr[i];
        s1[c] = fmaxf(r, 0.f);
    }
    __syncthreads();
    {
        float r = 0.f;
        const float* wr = w2 + (size_t)c*128;
        #pragma unroll 8
        for (int j = 0; j < 128; j++) r += s1[j]*wr[j];
        g_se[b*CC + c] = 1.0f / (1.0f + expf(-r));
    }
}

// =======================================================================
// mma.sync bf16 GEMM, 3-term hi/lo split, cp.async 2-stage pipeline.
// A staged raw fp32 in smem (split at frag load); W pre-split bf16.
// ASRC: 0=query gather, 1=g_xr, 2=g_attn, 3=conv gather
// EMODE: 2=q(scale+relu,split-head) 3=out(SE gate scatter)
//        4=conv(bias+LayerNorm -> g_xr) 5=fused k+v (ncol0 selects)
// =======================================================================
template<int ASRC, int EMODE, int WSEL, int MTILE, int NTOT, int KTOT, int LB>
__global__ __launch_bounds__(256, 2) void mm_tc(
    const float* __restrict__ Ain, const float* __restrict__ bias,
    const float* __restrict__ aux0, const float* __restrict__ aux1,
    float* __restrict__ outp)
{
    constexpr int WM = MTILE/32;
    constexpr int LROWS = 1<<LB;
    constexpr int ASTR_B = MTILE*36*4;     // fp32 A, stride 36 floats
    constexpr int WSTR_B = NTOT*80;        // bf16 W, stride 40 bf16 = 80B
    constexpr int STG_B  = ASTR_B + 2*WSTR_B;
    extern __shared__ char smb[];

    const int t = threadIdx.x, lane = t & 31, wid = t >> 5;
    const int g = lane >> 2, t4 = lane & 3;
    const int warp_m = wid & (WM-1);
    const int warp_n = wid / WM;
    const int ncol0 = blockIdx.y * NTOT;
    const int grow0 = blockIdx.x * MTILE;

    const __nv_bfloat16* Whi_src = (ASRC==3) ? g_wc_hi : (g_wp_hi + WSEL*65536);
    const __nv_bfloat16* Wlo_src = (ASRC==3) ? g_wc_lo : (g_wp_lo + WSEL*65536);

    auto stage = [&](int c, int s) {
        float* sA = (float*)(smb + s*STG_B);
        char*  sWh = smb + s*STG_B + ASTR_B;
        char*  sWl = sWh + WSTR_B;
        #pragma unroll
        for (int i = 0; i < MTILE/32; i++) {
            int idx = t + i*256;
            int row = idx >> 3, q4 = idx & 7;
            int r = grow0 + row;
            const float* p;
            if (ASRC == 3) {
                int b = r >> 8, ns = r & 255;
                int py = (ns >> 4)*2, px = (ns & 15)*2;
                int pp = c >> 3, ci0 = (c & 7)*32;
                int pix = (py + (pp>>1))*32 + px + (pp&1);
                p = Ain + (size_t)pix*(BB*CC) + b*CC + ci0 + q4*4;
            } else if (ASRC == 0) {
                p = Ain + (size_t)(r & (LROWS-1))*(BB*CC) + (r>>LB)*CC + c*32 + q4*4;
            } else {
                const float* base = (ASRC==1) ? g_xr : g_attn;
                p = base + (size_t)r*CC + c*32 + q4*4;
            }
            cp16(sA + row*36 + q4*4, p);
        }
        // W: per row 32 bf16 = 64B = 4 segs of 16B, hi+lo
        #pragma unroll
        for (int i = 0; i < NTOT/64; i++) {
            int idx = t + i*256;
            int row = idx >> 2, seg = idx & 3;
            size_t go = (size_t)(ncol0 + row)*KTOT + c*32 + seg*8;
            cp16(sWh + row*80 + seg*16, Whi_src + go);
            cp16(sWl + row*80 + seg*16, Wlo_src + go);
        }
        CP_COMMIT();
    };

    float acc[2][8][4];
    #pragma unroll
    for (int mt=0; mt<2; mt++)
        #pragma unroll
        for (int nt=0; nt<8; nt++)
            #pragma unroll
            for (int q=0; q<4; q++) acc[mt][nt][q] = 0.f;

    constexpr int NCH = KTOT/32;
    stage(0, 0);
    stage(1, 1);

    for (int c = 0; c < NCH; c++) {
        if (c < NCH-1) { CP_WAIT(1); } else { CP_WAIT(0); }
        __syncthreads();
        const int s = c & 1;
        float* sA = (float*)(smb + s*STG_B);
        char*  sWh = smb + s*STG_B + ASTR_B;
        char*  sWl = sWh + WSTR_B;
        #pragma unroll
        for (int ks = 0; ks < 2; ks++) {           // two k16 steps per 32-chunk
            uint32_t ah[2][4], al[2][4];
            #pragma unroll
            for (int mt=0; mt<2; mt++) {
                int rb = (warp_m*32 + mt*16 + g)*36 + ks*16 + 2*t4;
                float2 r0 = *(const float2*)&sA[rb];        // row g,   k..k+1
                float2 r1 = *(const float2*)&sA[rb+288];    // row g+8
                float2 r2 = *(const float2*)&sA[rb+8];      // row g,   k+8..9
                float2 r3 = *(const float2*)&sA[rb+296];    // row g+8
                splitb(r0.x, r0.y, ah[mt][0], al[mt][0]);
                splitb(r1.x, r1.y, ah[mt][1], al[mt][1]);
                splitb(r2.x, r2.y, ah[mt][2], al[mt][2]);
                splitb(r3.x, r3.y, ah[mt][3], al[mt][3]);
            }
            #pragma unroll
            for (int nt=0; nt<8; nt++) {
                int nb = (warp_n*64 + nt*8 + g)*80 + ks*32 + t4*4;
                uint32_t bh[2], bl[2];
                bh[0] = *(const uint32_t*)(sWh + nb);
                bh[1] = *(const uint32_t*)(sWh + nb + 16);
                bl[0] = *(const uint32_t*)(sWl + nb);
                bl[1] = *(const uint32_t*)(sWl + nb + 16);
                mma16(acc[0][nt], ah[0], bh);
                mma16(acc[1][nt], ah[1], bh);
                mma16(acc[0][nt], al[0], bh);
                mma16(acc[1][nt], al[1], bh);
                mma16(acc[0][nt], ah[0], bl);
                mma16(acc[1][nt], ah[1], bl);
            }
        }
        __syncthreads();
        if (c + 2 < NCH) stage(c+2, s);
    }

    // ================= epilogues =================
    if (EMODE == 4) {
        __shared__ float lnp[64][4], lnq[64][4], lnmu[64], lniv[64];
        float ps[2][2] = {{0.f,0.f},{0.f,0.f}};
        float pq[2][2] = {{0.f,0.f},{0.f,0.f}};
        #pragma unroll
        for (int mt=0; mt<2; mt++)
            #pragma unroll
            for (int nt=0; nt<8; nt++) {
                int gcol = warp_n*64 + nt*8 + t4*2;
                float2 bb = *(const float2*)(bias + gcol);
                float v0=acc[mt][nt][0]+bb.x, v1=acc[mt][nt][1]+bb.y;
                float v2=acc[mt][nt][2]+bb.x, v3=acc[mt][nt][3]+bb.y;
                acc[mt][nt][0]=v0; acc[mt][nt][1]=v1;
                acc[mt][nt][2]=v2; acc[mt][nt][3]=v3;
                ps[mt][0]+=v0+v1; pq[mt][0]+=v0*v0+v1*v1;
                ps[mt][1]+=v2+v3; pq[mt][1]+=v2*v2+v3*v3;
            }
        #pragma unroll
        for (int mt=0; mt<2; mt++)
            #pragma unroll
            for (int hf=0; hf<2; hf++) {
                float s = ps[mt][hf], q = pq[mt][hf];
                s += __shfl_xor_sync(0xffffffffu, s, 1);
                s += __shfl_xor_sync(0xffffffffu, s, 2);
                q += __shfl_xor_sync(0xffffffffu, q, 1);
                q += __shfl_xor_sync(0xffffffffu, q, 2);
                if (t4 == 0) {
                    int row = warp_m*32 + mt*16 + g + hf*8;
                    lnp[row][warp_n] = s; lnq[row][warp_n] = q;
                }
            }
        __syncthreads();
        if (t < 64) {
            float s = lnp[t][0]+lnp[t][1]+lnp[t][2]+lnp[t][3];
            float q = lnq[t][0]+lnq[t][1]+lnq[t][2]+lnq[t][3];
            float mu = s*(1.f/256.f);
            lnmu[t] = mu;
            lniv[t] = rsqrtf(q*(1.f/256.f) - mu*mu + 1e-5f);
        }
        __syncthreads();
        #pragma unroll
        for (int mt=0; mt<2; mt++) {
            int ra = warp_m*32 + mt*16 + g;
            float mua = lnmu[ra],   iva = lniv[ra];
            float mub = lnmu[ra+8], ivb = lniv[ra+8];
            #pragma unroll
            for (int nt=0; nt<8; nt++) {
                int gcol = warp_n*64 + nt*8 + t4*2;
                float2 gv = *(const float2*)(aux0 + gcol);
                float2 bv = *(const float2*)(aux1 + gcol);
                float o0 = (acc[mt][nt][0]-mua)*iva*gv.x + bv.x;
                float o1 = (acc[mt][nt][1]-mua)*iva*gv.y + bv.y;
                float o2 = (acc[mt][nt][2]-mub)*ivb*gv.x + bv.x;
                float o3 = (acc[mt][nt][3]-mub)*ivb*gv.y + bv.y;
                *(float2*)(g_xr + (size_t)(grow0+ra)*CC + gcol)   = make_float2(o0,o1);
                *(float2*)(g_xr + (size_t)(grow0+ra+8)*CC + gcol) = make_float2(o2,o3);
            }
        }
    } else {
        const bool isv = (EMODE == 5) && (ncol0 >= 256);
        #pragma unroll
        for (int mt=0; mt<2; mt++) {
            int r1 = grow0 + warp_m*32 + mt*16 + g;
            int b1 = r1 >> LB;
            int n1 = r1 & (LROWS-1);
            int n2 = n1 + 8;
            #pragma unroll
            for (int nt=0; nt<8; nt++) {
                int gcol = ncol0 + warp_n*64 + nt*8 + t4*2;
                float2 bb = *(const float2*)(bias + gcol);
                float v0=acc[mt][nt][0]+bb.x, v1=acc[mt][nt][1]+bb.y;
                float v2=acc[mt][nt][2]+bb.x, v3=acc[mt][nt][3]+bb.y;
                if (EMODE == 2) {
                    const float sc = 0.17677669529663687f;
                    v0=fmaxf(v0*sc,0.f); v1=fmaxf(v1*sc,0.f);
                    v2=fmaxf(v2*sc,0.f); v3=fmaxf(v3*sc,0.f);
                }
                if (EMODE == 5 && !isv) {
                    v0=fmaxf(v0,0.f); v1=fmaxf(v1,0.f);
                    v2=fmaxf(v2,0.f); v3=fmaxf(v3,0.f);
                }
                if (EMODE == 3) {
                    float2 se = *(const float2*)(g_se + b1*CC + gcol);
                    *(float2*)(outp + ((size_t)n1*BB + b1)*CC + gcol) = make_float2(v0*se.x, v1*se.y);
                    *(float2*)(outp + ((size_t)n2*BB + b1)*CC + gcol) = make_float2(v2*se.x, v3*se.y);
                } else {
                    int hcol = gcol & 255;
                    int h = hcol >> 5, d = hcol & 31;
                    float* gb = (EMODE==2) ? g_q : (isv ? g_v : g_k);
                    size_t base = ((size_t)(b1*NH + h) << LB);
                    *(float2*)(gb + (base + n1)*HD + d) = make_float2(v0,v1);
                    *(float2*)(gb + (base + n2)*HD + d) = make_float2(v2,v3);
                }
            }
        }
    }
}

// ---------------- kv accumulation ----------------
__global__ __launch_bounds__(256) void kv_kernel()
{
    const int bh = blockIdx.x;
    const int t  = threadIdx.x;
    const int m  = t & 31, dq = t >> 5;
    __shared__ __align__(16) float ks[128*32];
    __shared__ __align__(16) float vs[128*32];
    __shared__ float wsm[4][128];
    float acc[4][4];
    #pragma unroll
    for (int g = 0; g < 4; g++)
        #pragma unroll
        for (int di = 0; di < 4; di++) acc[g][di] = 0.f;
    float ksacc = 0.f;

    for (int half = 0; half < 2; half++) {
        __syncthreads();
        const float4* kp = (const float4*)(g_k + ((size_t)bh*NSAMP + half*128)*HD);
        const float4* vp = (const float4*)(g_v + ((size_t)bh*NSAMP + half*128)*HD);
        float4* ks4 = (float4*)ks;
        float4* vs4 = (float4*)vs;
        #pragma unroll
        for (int i = 0; i < 4; i++) {
            ks4[t + i*256] = kp[t + i*256];
            vs4[t + i*256] = vp[t + i*256];
        }
        if (t < 128) {
            const int ns = half*128 + t;
            const float aa = 1.57079632679489662f * (float)(ns >> 4) * (1.f/16.f);
            const float ab = 1.57079632679489662f * (float)(ns & 15) * (1.f/16.f);
            wsm[0][t] = cosf(aa); wsm[1][t] = sinf(aa);
            wsm[2][t] = cosf(ab); wsm[3][t] = sinf(ab);
        }
        __syncthreads();
        #pragma unroll 4
        for (int nl = 0; nl < 128; nl++) {
            const float wv = vs[nl*32 + m];
            float4 kd = *(const float4*)&ks[nl*32 + dq*4];
            float w0 = wsm[0][nl]*wv, w1 = wsm[1][nl]*wv;
            float w2 = wsm[2][nl]*wv, w3 = wsm[3][nl]*wv;
            acc[0][0]+=kd.x*w0; acc[0][1]+=kd.y*w0; acc[0][2]+=kd.z*w0; acc[0][3]+=kd.w*w0;
            acc[1][0]+=kd.x*w1; acc[1][1]+=kd.y*w1; acc[1][2]+=kd.z*w1; acc[1][3]+=kd.w*w1;
            acc[2][0]+=kd.x*w2; acc[2][1]+=kd.y*w2; acc[2][2]+=kd.z*w2; acc[2][3]+=kd.w*w2;
            acc[3][0]+=kd.x*w3; acc[3][1]+=kd.y*w3; acc[3][2]+=kd.z*w3; acc[3][3]+=kd.w*w3;
        }
        if (t < 128) {
            const int g = t >> 5, d = t & 31;
            float s = 0.f;
            #pragma unroll 8
            for (int nl = 0; nl < 128; nl++) s += wsm[g][nl] * ks[nl*32 + d];
            ksacc += s;
        }
    }
    float* kvp = g_kv + (size_t)bh*4096;
    #pragma unroll
    for (int g = 0; g < 4; g++)
        #pragma unroll
        for (int di = 0; di < 4; di++)
            kvp[(g*32 + dq*4 + di)*32 + m] = acc[g][di];
    if (t < 128) g_ksum[bh*128 + t] = ksacc;
}

// ---------------- per-query attention: 4 queries x 8 m-cols per thread ----------------
__global__ __launch_bounds__(256) void attn_kernel()
{
    const int bh = blockIdx.y;
    const int mc = blockIdx.x;
    const int t  = threadIdx.x;
    __shared__ __align__(16) float kvs[4][32][8];
    __shared__ float ksums[128];
    {
        const float* kvp = g_kv + (size_t)bh*4096 + mc*8;
        for (int i = t; i < 1024; i += 256) {
            int gg = i >> 8, rem = i & 255, d = rem >> 3, m = rem & 7;
            kvs[gg][d][m] = kvp[(gg*32 + d)*32 + m];
        }
        if (t < 128) ksums[t] = g_ksum[bh*128 + t];
    }
    __syncthreads();

    float qv[4][32];
    float u[4][4];
    #pragma unroll
    for (int j = 0; j < 4; j++) {
        const int n = j*256 + t;
        const float4* qp = (const float4*)(g_q + ((size_t)bh*NN + n)*HD);
        #pragma unroll
        for (int i = 0; i < 8; i++) {
            float4 v = qp[i];
            qv[j][i*4+0]=v.x; qv[j][i*4+1]=v.y; qv[j][i*4+2]=v.z; qv[j][i*4+3]=v.w;
        }
        const float aa = 1.57079632679489662f * (float)(n >> 5) * (1.f/32.f);
        const float ab = 1.57079632679489662f * (float)(n & 31) * (1.f/32.f);
        u[j][0]=cosf(aa); u[j][1]=sinf(aa); u[j][2]=cosf(ab); u[j][3]=sinf(ab);
    }

    float inv[4];
    #pragma unroll
    for (int j = 0; j < 4; j++) {
        float den = 0.f;
        #pragma unroll
        for (int gg = 0; gg < 4; gg++) {
            float s = 0.f;
            #pragma unroll
            for (int d = 0; d < 32; d++) s += qv[j][d]*ksums[gg*32+d];
            den += u[j][gg]*s;
        }
        float ad = fminf(fmaxf(fabsf(den), 1e-4f), 1e4f);
        inv[j] = 1.0f / copysignf(ad, den);
    }

    float acc[4][8];
    #pragma unroll
    for (int j = 0; j < 4; j++)
        #pragma unroll
        for (int m = 0; m < 8; m++) acc[j][m] = 0.f;

    #pragma unroll 1
    for (int gg = 0; gg < 4; gg++) {
        #pragma unroll
        for (int d = 0; d < 32; d++) {
            float4 k0 = *(const float4*)&kvs[gg][d][0];
            float4 k1 = *(const float4*)&kvs[gg][d][4];
            #pragma unroll
            for (int j = 0; j < 4; j++) {
                const float coef = u[j][gg] * qv[j][d];
                acc[j][0] += coef*k0.x; acc[j][1] += coef*k0.y;
                acc[j][2] += coef*k0.z; acc[j][3] += coef*k0.w;
                acc[j][4] += coef*k1.x; acc[j][5] += coef*k1.y;
                acc[j][6] += coef*k1.z; acc[j][7] += coef*k1.w;
            }
        }
    }

    const int b = bh >> 3, h = bh & 7;
    #pragma unroll
    for (int j = 0; j < 4; j++) {
        const int n = j*256 + t;
        float4* op = (float4*)(g_attn + ((size_t)b*NN + n)*CC + h*HD + mc*8);
        op[0] = make_float4(acc[j][0]*inv[j], acc[j][1]*inv[j],
                            acc[j][2]*inv[j], acc[j][3]*inv[j]);
        op[1] = make_float4(acc[j][4]*inv[j], acc[j][5]*inv[j],
                            acc[j][6]*inv[j], acc[j][7]*inv[j]);
    }
}

// ---------------- launch ----------------
#define SM_PROJ (2*(128*36*4 + 2*128*80))
#define SM_CONV (2*(64*36*4  + 2*256*80))

extern "C" void kernel_launch(void* const* d_in, const int* in_sizes, int n_in,
                              void* d_out, int out_size)
{
    const float *query=0,*ipw=0,*ipb=0,*srw=0,*srb=0,*ng=0,*nb=0,*outw=0,*outb=0,*sew1=0,*sew2=0;
    int nbig = 0, n256 = 0, n32k = 0;
    for (int i = 0; i < n_in; i++) {
        const int s = in_sizes[i];
        const float* p = (const float*)d_in[i];
        if (s == 16777216)      { if (nbig++ == 0) query = p; }
        else if (s == 196608)   ipw = p;
        else if (s == 768)      ipb = p;
        else if (s == 262144)   srw = p;
        else if (s == 65536)    outw = p;
        else if (s == 32768)    { if (n32k++ == 0) sew1 = p; else sew2 = p; }
        else if (s == 256) {
            switch (n256++) {
                case 0: srb = p; break;
                case 1: ng  = p; break;
                case 2: nb  = p; break;
                case 3: outb= p; break;
            }
        }
    }
    float* out = (float*)d_out;

    cudaFuncSetAttribute(mm_tc<3,4,0,64,256,1024,8>,  cudaFuncAttributeMaxDynamicSharedMemorySize, SM_CONV);
    cudaFuncSetAttribute(mm_tc<0,2,0,128,128,256,10>, cudaFuncAttributeMaxDynamicSharedMemorySize, SM_PROJ);
    cudaFuncSetAttribute(mm_tc<1,5,1,128,128,256,8>,  cudaFuncAttributeMaxDynamicSharedMemorySize, SM_PROJ);
    cudaFuncSetAttribute(mm_tc<2,3,3,128,128,256,10>, cudaFuncAttributeMaxDynamicSharedMemorySize, SM_PROJ);

    prep_kernel<<<2048, 256>>>(ipw, outw, srw);
    se_kernel<<<BB, 256>>>(query, sew1, sew2);
    // conv + LN  (M=16384 rows of 64)
    mm_tc<3,4,0,64,256,1024,8><<<256, 256, SM_CONV>>>(query, srb, ng, nb, nullptr);
    // q proj (M=65536)
    mm_tc<0,2,0,128,128,256,10><<<dim3(512,2), 256, SM_PROJ>>>(query, ipb, nullptr, nullptr, nullptr);
    // fused k+v proj (M=16384, N=512)
    mm_tc<1,5,1,128,128,256,8><<<dim3(128,4), 256, SM_PROJ>>>(nullptr, ipb + CC, nullptr, nullptr, nullptr);
    kv_kernel<<<NBH, 256>>>();
    attn_kernel<<<dim3(4, NBH), 256>>>();
    // out proj (M=65536)
    mm_tc<2,3,3,128,128,256,10><<<dim3(512,2), 256, SM_PROJ>>>(nullptr, outb, nullptr, nullptr, out);
    (void)out_size;
}

// round 15
// speedup vs baseline: 2.6261x; 1.1954x over previous
#include <cuda_runtime.h>
#include <cuda_bf16.h>
#include <math.h>
#include <stdint.h>

#define BB 64
#define NN 1024
#define CC 256
#define NSAMP 256
#define NH 8
#define HD 32
#define NBH (BB*NH)

__device__ float g_xr[BB*NSAMP*CC];
__device__ float g_q[NBH*NN*HD];
__device__ float g_k[NBH*NSAMP*HD];
__device__ float g_v[NBH*NSAMP*HD];
__device__ float g_ksum[NBH*4*HD];
__device__ float g_attn[BB*NN*CC];
__device__ float g_se[BB*CC];
__device__ __nv_bfloat16 g_wc_hi[256*1024];
__device__ __nv_bfloat16 g_wc_lo[256*1024];
__device__ __nv_bfloat16 g_wp_hi[4*256*256];
__device__ __nv_bfloat16 g_wp_lo[4*256*256];
__device__ __nv_bfloat16 g_kvT_hi[NBH*32*128];
__device__ __nv_bfloat16 g_kvT_lo[NBH*32*128];

// split x,y into packed bf16 hi pair + bf16 residual pair (lo16 = first elem)
__device__ __forceinline__ void splitb(float x, float y, uint32_t& hi, uint32_t& lo) {
    uint32_t h; asm("cvt.rn.bf16x2.f32 %0, %1, %2;" : "=r"(h) : "f"(y), "f"(x));
    float hx = __uint_as_float(h << 16);
    float hy = __uint_as_float(h & 0xFFFF0000u);
    float rx = x - hx, ry = y - hy;
    uint32_t l; asm("cvt.rn.bf16x2.f32 %0, %1, %2;" : "=r"(l) : "f"(ry), "f"(rx));
    hi = h; lo = l;
}

__device__ __forceinline__ void mma16(float* d, const uint32_t* a, const uint32_t* b) {
    asm("mma.sync.aligned.m16n8k16.row.col.f32.bf16.bf16.f32 "
        "{%0,%1,%2,%3}, {%4,%5,%6,%7}, {%8,%9}, {%0,%1,%2,%3};"
        : "+f"(d[0]), "+f"(d[1]), "+f"(d[2]), "+f"(d[3])
        : "r"(a[0]), "r"(a[1]), "r"(a[2]), "r"(a[3]), "r"(b[0]), "r"(b[1]));
}

__device__ __forceinline__ void cp16(void* sm, const void* gm) {
    uint32_t a = (uint32_t)__cvta_generic_to_shared(sm);
    asm volatile("cp.async.cg.shared.global [%0], [%1], 16;" :: "r"(a), "l"(gm) : "memory");
}
#define CP_COMMIT() asm volatile("cp.async.commit_group;" ::: "memory")
#define CP_WAIT(n)  asm volatile("cp.async.wait_group %0;" :: "n"(n) : "memory")

// ---------------- weight prep: reorder + bf16 hi/lo split ----------------
__global__ __launch_bounds__(256) void prep_kernel(
    const float* __restrict__ ipw, const float* __restrict__ outw,
    const float* __restrict__ srw)
{
    int idx = blockIdx.x*256 + threadIdx.x;
    float v;
    __nv_bfloat16 *dh, *dl;
    if (idx < 262144) {
        int oc = idx >> 10, k = idx & 1023, p = k >> 8, ci = k & 255;
        v = srw[oc*1024 + ci*4 + p];
        dh = g_wc_hi + idx; dl = g_wc_lo + idx;
    } else {
        int j = idx - 262144;
        int m = j >> 16;
        const float* src = (m < 3) ? (ipw + m*65536) : outw;
        v = src[j & 65535];
        dh = g_wp_hi + j; dl = g_wp_lo + j;
    }
    __nv_bfloat16 h = __float2bfloat16(v);
    float hf = __uint_as_float(((uint32_t)__bfloat16_as_ushort(h)) << 16);
    *dh = h;
    *dl = __float2bfloat16(v - hf);
}

// ---------------- SE ----------------
__global__ __launch_bounds__(256) void se_kernel(
    const float* __restrict__ query, const float* __restrict__ w1,
    const float* __restrict__ w2)
{
    const int b = blockIdx.x, c = threadIdx.x;
    const float* p = query + (size_t)b*CC + c;
    float a0=0.f,a1=0.f,a2=0.f,a3=0.f;
    for (int n = 0; n < NN; n += 4) {
        a0 += p[(size_t)(n+0)*(BB*CC)];
        a1 += p[(size_t)(n+1)*(BB*CC)];
        a2 += p[(size_t)(n+2)*(BB*CC)];
        a3 += p[(size_t)(n+3)*(BB*CC)];
    }
    __shared__ float sm[CC];
    __shared__ float s1[CC/2];
    sm[c] = (a0+a1+a2+a3) * (1.0f/NN);
    __syncthreads();
    if (c < 128) {
        float r = 0.f;
        const float* wr = w1 + (size_t)c*CC;
        #pragma unroll 8
        for (int i = 0; i < CC; i++) r += sm[i]*wr[i];
        s1[c] = fmaxf(r, 0.f);
    }
    __syncthreads();
    {
        float r = 0.f;
        const float* wr = w2 + (size_t)c*128;
        #pragma unroll 8
        for (int j = 0; j < 128; j++) r += s1[j]*wr[j];
        g_se[b*CC + c] = 1.0f / (1.0f + expf(-r));
    }
}

// =======================================================================
// mma.sync bf16 GEMM, 3-term hi/lo split, cp.async 2-stage pipeline.
// =======================================================================
template<int ASRC, int EMODE, int WSEL, int MTILE, int NTOT, int KTOT, int LB>
__global__ __launch_bounds__(256, 2) void mm_tc(
    const float* __restrict__ Ain, const float* __restrict__ bias,
    const float* __restrict__ aux0, const float* __restrict__ aux1,
    float* __restrict__ outp)
{
    constexpr int WM = MTILE/32;
    constexpr int LROWS = 1<<LB;
    constexpr int ASTR_B = MTILE*36*4;
    constexpr int WSTR_B = NTOT*80;
    constexpr int STG_B  = ASTR_B + 2*WSTR_B;
    extern __shared__ char smb[];

    const int t = threadIdx.x, lane = t & 31, wid = t >> 5;
    const int g = lane >> 2, t4 = lane & 3;
    const int warp_m = wid & (WM-1);
    const int warp_n = wid / WM;
    const int ncol0 = blockIdx.y * NTOT;
    const int grow0 = blockIdx.x * MTILE;

    const __nv_bfloat16* Whi_src = (ASRC==3) ? g_wc_hi : (g_wp_hi + WSEL*65536);
    const __nv_bfloat16* Wlo_src = (ASRC==3) ? g_wc_lo : (g_wp_lo + WSEL*65536);

    auto stage = [&](int c, int s) {
        float* sA = (float*)(smb + s*STG_B);
        char*  sWh = smb + s*STG_B + ASTR_B;
        char*  sWl = sWh + WSTR_B;
        #pragma unroll
        for (int i = 0; i < MTILE/32; i++) {
            int idx = t + i*256;
            int row = idx >> 3, q4 = idx & 7;
            int r = grow0 + row;
            const float* p;
            if (ASRC == 3) {
                int b = r >> 8, ns = r & 255;
                int py = (ns >> 4)*2, px = (ns & 15)*2;
                int pp = c >> 3, ci0 = (c & 7)*32;
                int pix = (py + (pp>>1))*32 + px + (pp&1);
                p = Ain + (size_t)pix*(BB*CC) + b*CC + ci0 + q4*4;
            } else if (ASRC == 0) {
                p = Ain + (size_t)(r & (LROWS-1))*(BB*CC) + (r>>LB)*CC + c*32 + q4*4;
            } else {
                const float* base = (ASRC==1) ? g_xr : g_attn;
                p = base + (size_t)r*CC + c*32 + q4*4;
            }
            cp16(sA + row*36 + q4*4, p);
        }
        #pragma unroll
        for (int i = 0; i < NTOT/64; i++) {
            int idx = t + i*256;
            int row = idx >> 2, seg = idx & 3;
            size_t go = (size_t)(ncol0 + row)*KTOT + c*32 + seg*8;
            cp16(sWh + row*80 + seg*16, Whi_src + go);
            cp16(sWl + row*80 + seg*16, Wlo_src + go);
        }
        CP_COMMIT();
    };

    float acc[2][8][4];
    #pragma unroll
    for (int mt=0; mt<2; mt++)
        #pragma unroll
        for (int nt=0; nt<8; nt++)
            #pragma unroll
            for (int q=0; q<4; q++) acc[mt][nt][q] = 0.f;

    constexpr int NCH = KTOT/32;
    stage(0, 0);
    stage(1, 1);

    for (int c = 0; c < NCH; c++) {
        if (c < NCH-1) { CP_WAIT(1); } else { CP_WAIT(0); }
        __syncthreads();
        const int s = c & 1;
        float* sA = (float*)(smb + s*STG_B);
        char*  sWh = smb + s*STG_B + ASTR_B;
        char*  sWl = sWh + WSTR_B;
        #pragma unroll
        for (int ks = 0; ks < 2; ks++) {
            uint32_t ah[2][4], al[2][4];
            #pragma unroll
            for (int mt=0; mt<2; mt++) {
                int rb = (warp_m*32 + mt*16 + g)*36 + ks*16 + 2*t4;
                float2 r0 = *(const float2*)&sA[rb];
                float2 r1 = *(const float2*)&sA[rb+288];
                float2 r2 = *(const float2*)&sA[rb+8];
                float2 r3 = *(const float2*)&sA[rb+296];
                splitb(r0.x, r0.y, ah[mt][0], al[mt][0]);
                splitb(r1.x, r1.y, ah[mt][1], al[mt][1]);
                splitb(r2.x, r2.y, ah[mt][2], al[mt][2]);
                splitb(r3.x, r3.y, ah[mt][3], al[mt][3]);
            }
            #pragma unroll
            for (int nt=0; nt<8; nt++) {
                int nb = (warp_n*64 + nt*8 + g)*80 + ks*32 + t4*4;
                uint32_t bh[2], bl[2];
                bh[0] = *(const uint32_t*)(sWh + nb);
                bh[1] = *(const uint32_t*)(sWh + nb + 16);
                bl[0] = *(const uint32_t*)(sWl + nb);
                bl[1] = *(const uint32_t*)(sWl + nb + 16);
                mma16(acc[0][nt], ah[0], bh);
                mma16(acc[1][nt], ah[1], bh);
                mma16(acc[0][nt], al[0], bh);
                mma16(acc[1][nt], al[1], bh);
                mma16(acc[0][nt], ah[0], bl);
                mma16(acc[1][nt], ah[1], bl);
            }
        }
        __syncthreads();
        if (c + 2 < NCH) stage(c+2, s);
    }

    // ================= epilogues =================
    if (EMODE == 4) {
        __shared__ float lnp[64][4], lnq[64][4], lnmu[64], lniv[64];
        float ps[2][2] = {{0.f,0.f},{0.f,0.f}};
        float pq[2][2] = {{0.f,0.f},{0.f,0.f}};
        #pragma unroll
        for (int mt=0; mt<2; mt++)
            #pragma unroll
            for (int nt=0; nt<8; nt++) {
                int gcol = warp_n*64 + nt*8 + t4*2;
                float2 bb = *(const float2*)(bias + gcol);
                float v0=acc[mt][nt][0]+bb.x, v1=acc[mt][nt][1]+bb.y;
                float v2=acc[mt][nt][2]+bb.x, v3=acc[mt][nt][3]+bb.y;
                acc[mt][nt][0]=v0; acc[mt][nt][1]=v1;
                acc[mt][nt][2]=v2; acc[mt][nt][3]=v3;
                ps[mt][0]+=v0+v1; pq[mt][0]+=v0*v0+v1*v1;
                ps[mt][1]+=v2+v3; pq[mt][1]+=v2*v2+v3*v3;
            }
        #pragma unroll
        for (int mt=0; mt<2; mt++)
            #pragma unroll
            for (int hf=0; hf<2; hf++) {
                float s = ps[mt][hf], q = pq[mt][hf];
                s += __shfl_xor_sync(0xffffffffu, s, 1);
                s += __shfl_xor_sync(0xffffffffu, s, 2);
                q += __shfl_xor_sync(0xffffffffu, q, 1);
                q += __shfl_xor_sync(0xffffffffu, q, 2);
                if (t4 == 0) {
                    int row = warp_m*32 + mt*16 + g + hf*8;
                    lnp[row][warp_n] = s; lnq[row][warp_n] = q;
                }
            }
        __syncthreads();
        if (t < 64) {
            float s = lnp[t][0]+lnp[t][1]+lnp[t][2]+lnp[t][3];
            float q = lnq[t][0]+lnq[t][1]+lnq[t][2]+lnq[t][3];
            float mu = s*(1.f/256.f);
            lnmu[t] = mu;
            lniv[t] = rsqrtf(q*(1.f/256.f) - mu*mu + 1e-5f);
        }
        __syncthreads();
        #pragma unroll
        for (int mt=0; mt<2; mt++) {
            int ra = warp_m*32 + mt*16 + g;
            float mua = lnmu[ra],   iva = lniv[ra];
            float mub = lnmu[ra+8], ivb = lniv[ra+8];
            #pragma unroll
            for (int nt=0; nt<8; nt++) {
                int gcol = warp_n*64 + nt*8 + t4*2;
                float2 gv = *(const float2*)(aux0 + gcol);
                float2 bv = *(const float2*)(aux1 + gcol);
                float o0 = (acc[mt][nt][0]-mua)*iva*gv.x + bv.x;
                float o1 = (acc[mt][nt][1]-mua)*iva*gv.y + bv.y;
                float o2 = (acc[mt][nt][2]-mub)*ivb*gv.x + bv.x;
                float o3 = (acc[mt][nt][3]-mub)*ivb*gv.y + bv.y;
                *(float2*)(g_xr + (size_t)(grow0+ra)*CC + gcol)   = make_float2(o0,o1);
                *(float2*)(g_xr + (size_t)(grow0+ra+8)*CC + gcol) = make_float2(o2,o3);
            }
        }
    } else {
        const bool isv = (EMODE == 5) && (ncol0 >= 256);
        #pragma unroll
        for (int mt=0; mt<2; mt++) {
            int r1 = grow0 + warp_m*32 + mt*16 + g;
            int b1 = r1 >> LB;
            int n1 = r1 & (LROWS-1);
            int n2 = n1 + 8;
            #pragma unroll
            for (int nt=0; nt<8; nt++) {
                int gcol = ncol0 + warp_n*64 + nt*8 + t4*2;
                float2 bb = *(const float2*)(bias + gcol);
                float v0=acc[mt][nt][0]+bb.x, v1=acc[mt][nt][1]+bb.y;
                float v2=acc[mt][nt][2]+bb.x, v3=acc[mt][nt][3]+bb.y;
                if (EMODE == 2) {
                    const float sc = 0.17677669529663687f;
                    v0=fmaxf(v0*sc,0.f); v1=fmaxf(v1*sc,0.f);
                    v2=fmaxf(v2*sc,0.f); v3=fmaxf(v3*sc,0.f);
                }
                if (EMODE == 5 && !isv) {
                    v0=fmaxf(v0,0.f); v1=fmaxf(v1,0.f);
                    v2=fmaxf(v2,0.f); v3=fmaxf(v3,0.f);
                }
                if (EMODE == 3) {
                    float2 se = *(const float2*)(g_se + b1*CC + gcol);
                    *(float2*)(outp + ((size_t)n1*BB + b1)*CC + gcol) = make_float2(v0*se.x, v1*se.y);
                    *(float2*)(outp + ((size_t)n2*BB + b1)*CC + gcol) = make_float2(v2*se.x, v3*se.y);
                } else {
                    int hcol = gcol & 255;
                    int h = hcol >> 5, d = hcol & 31;
                    float* gb = (EMODE==2) ? g_q : (isv ? g_v : g_k);
                    size_t base = ((size_t)(b1*NH + h) << LB);
                    *(float2*)(gb + (base + n1)*HD + d) = make_float2(v0,v1);
                    *(float2*)(gb + (base + n2)*HD + d) = make_float2(v2,v3);
                }
            }
        }
    }
}

// ---------------- kv accumulation -> bf16 kvT hi/lo + ksum ----------------
__global__ __launch_bounds__(256) void kv_kernel()
{
    const int bh = blockIdx.x;
    const int t  = threadIdx.x;
    const int m  = t & 31, dq = t >> 5;
    __shared__ __align__(16) float ks[128*32];
    __shared__ __align__(16) float vs[128*32];
    __shared__ float wsm[4][128];
    float acc[4][4];
    #pragma unroll
    for (int g = 0; g < 4; g++)
        #pragma unroll
        for (int di = 0; di < 4; di++) acc[g][di] = 0.f;
    float ksacc = 0.f;

    for (int half = 0; half < 2; half++) {
        __syncthreads();
        const float4* kp = (const float4*)(g_k + ((size_t)bh*NSAMP + half*128)*HD);
        const float4* vp = (const float4*)(g_v + ((size_t)bh*NSAMP + half*128)*HD);
        float4* ks4 = (float4*)ks;
        float4* vs4 = (float4*)vs;
        #pragma unroll
        for (int i = 0; i < 4; i++) {
            ks4[t + i*256] = kp[t + i*256];
            vs4[t + i*256] = vp[t + i*256];
        }
        if (t < 128) {
            const int ns = half*128 + t;
            const float aa = 1.57079632679489662f * (float)(ns >> 4) * (1.f/16.f);
            const float ab = 1.57079632679489662f * (float)(ns & 15) * (1.f/16.f);
            wsm[0][t] = cosf(aa); wsm[1][t] = sinf(aa);
            wsm[2][t] = cosf(ab); wsm[3][t] = sinf(ab);
        }
        __syncthreads();
        #pragma unroll 4
        for (int nl = 0; nl < 128; nl++) {
            const float wv = vs[nl*32 + m];
            float4 kd = *(const float4*)&ks[nl*32 + dq*4];
            float w0 = wsm[0][nl]*wv, w1 = wsm[1][nl]*wv;
            float w2 = wsm[2][nl]*wv, w3 = wsm[3][nl]*wv;
            acc[0][0]+=kd.x*w0; acc[0][1]+=kd.y*w0; acc[0][2]+=kd.z*w0; acc[0][3]+=kd.w*w0;
            acc[1][0]+=kd.x*w1; acc[1][1]+=kd.y*w1; acc[1][2]+=kd.z*w1; acc[1][3]+=kd.w*w1;
            acc[2][0]+=kd.x*w2; acc[2][1]+=kd.y*w2; acc[2][2]+=kd.z*w2; acc[2][3]+=kd.w*w2;
            acc[3][0]+=kd.x*w3; acc[3][1]+=kd.y*w3; acc[3][2]+=kd.z*w3; acc[3][3]+=kd.w*w3;
        }
        if (t < 128) {
            const int g = t >> 5, d = t & 31;
            float s = 0.f;
            #pragma unroll 8
            for (int nl = 0; nl < 128; nl++) s += wsm[g][nl] * ks[nl*32 + d];
            ksacc += s;
        }
    }
    // write kvT (row m, cols d' = g*32+dq*4+di) as bf16 hi/lo packed pairs
    __nv_bfloat16* dh = g_kvT_hi + (size_t)bh*4096 + m*128;
    __nv_bfloat16* dl = g_kvT_lo + (size_t)bh*4096 + m*128;
    #pragma unroll
    for (int g = 0; g < 4; g++) {
        #pragma unroll
        for (int pr = 0; pr < 2; pr++) {
            float v0 = acc[g][pr*2], v1 = acc[g][pr*2+1];
            uint32_t hi, lo;
            splitb(v0, v1, hi, lo);
            int dp = g*32 + dq*4 + pr*2;
            *(uint32_t*)(dh + dp) = hi;
            *(uint32_t*)(dl + dp) = lo;
        }
    }
    if (t < 128) g_ksum[bh*128 + t] = ksacc;
}

// ---------------- attention: bf16x3 mma over A=u*q (128x128), B=kvT (32x128) ----------------
#define AQS 36     // q smem stride (floats)
#define AST 68     // A/B smem stride (uint32)
__global__ __launch_bounds__(256, 2) void attn_tc()
{
    const int bh = blockIdx.y;
    const int n0 = blockIdx.x * 128;
    const int t = threadIdx.x, lane = t & 31, wid = t >> 5;
    const int g = lane >> 2, t4 = lane & 3;

    extern __shared__ char smb[];
    float*    qs   = (float*)smb;                       // 128*36*4   = 18432
    uint32_t* Ah   = (uint32_t*)(smb + 18432);          // 128*68*4   = 34816
    uint32_t* Al   = Ah + 128*AST;                      // 34816
    uint32_t* Bh   = Al + 128*AST;                      // 32*68*4    = 8704
    uint32_t* Bl   = Bh + 32*AST;                       // 8704
    float*    us   = (float*)(Bl + 32*AST);             // 128*4*4    = 2048
    float*    invs = us + 512;                          // 512
    float*    ksm  = invs + 128;                        // 512

    const float* qsrc = g_q + ((size_t)bh*NN + n0)*HD;
    for (int i = t; i < 1024; i += 256) {
        int row = i >> 3, seg = i & 7;
        cp16(qs + row*AQS + seg*4, qsrc + row*32 + seg*4);
    }
    const __nv_bfloat16* bsh = g_kvT_hi + (size_t)bh*4096;
    const __nv_bfloat16* bsl = g_kvT_lo + (size_t)bh*4096;
    for (int i = t; i < 512; i += 256) {
        int row = i >> 4, seg = i & 15;
        cp16((char*)(Bh + row*AST) + seg*16, bsh + row*128 + seg*8);
        cp16((char*)(Bl + row*AST) + seg*16, bsl + row*128 + seg*8);
    }
    if (t < 128) {
        int n = n0 + t;
        const float aa = 1.57079632679489662f * (float)(n >> 5) * (1.f/32.f);
        const float ab = 1.57079632679489662f * (float)(n & 31) * (1.f/32.f);
        us[t*4+0]=cosf(aa); us[t*4+1]=sinf(aa); us[t*4+2]=cosf(ab); us[t*4+3]=sinf(ab);
    } else {
        ksm[t-128] = g_ksum[bh*128 + (t-128)];
    }
    CP_COMMIT(); CP_WAIT(0);
    __syncthreads();

    // build A = u_g(n) * q[n][d]  (bf16 hi/lo pairs)
    for (int i = t; i < 8192; i += 256) {
        int row = i >> 6, j = i & 63;
        int d0 = 2*j, gg = d0 >> 5, d = d0 & 31;
        float uf = us[row*4+gg];
        float q0 = qs[row*AQS+d], q1 = qs[row*AQS+d+1];
        uint32_t hi, lo;
        splitb(uf*q0, uf*q1, hi, lo);
        Ah[row*AST + j] = hi;
        Al[row*AST + j] = lo;
    }
    // denominators
    if (t < 128) {
        float den = 0.f;
        #pragma unroll
        for (int gg = 0; gg < 4; gg++) {
            float s = 0.f;
            #pragma unroll 8
            for (int d = 0; d < 32; d++) s += qs[t*AQS+d]*ksm[gg*32+d];
            den += us[t*4+gg]*s;
        }
        float ad = fminf(fmaxf(fabsf(den), 1e-4f), 1e4f);
        invs[t] = 1.0f / copysignf(ad, den);
    }
    __syncthreads();

    float acc[4][4];
    #pragma unroll
    for (int nt=0; nt<4; nt++)
        #pragma unroll
        for (int q=0; q<4; q++) acc[nt][q] = 0.f;

    #pragma unroll
    for (int ks = 0; ks < 8; ks++) {
        uint32_t ah[4], al[4];
        int rb = (wid*16 + g)*AST + ks*8 + t4;
        ah[0]=Ah[rb]; ah[1]=Ah[rb+8*AST]; ah[2]=Ah[rb+4]; ah[3]=Ah[rb+8*AST+4];
        al[0]=Al[rb]; al[1]=Al[rb+8*AST]; al[2]=Al[rb+4]; al[3]=Al[rb+8*AST+4];
        #pragma unroll
        for (int nt=0; nt<4; nt++) {
            int nb = (nt*8 + g)*AST + ks*8 + t4;
            uint32_t bh2[2], bl2[2];
            bh2[0]=Bh[nb]; bh2[1]=Bh[nb+4];
            bl2[0]=Bl[nb]; bl2[1]=Bl[nb+4];
            mma16(acc[nt], ah, bh2);
            mma16(acc[nt], al, bh2);
            mma16(acc[nt], ah, bl2);
        }
    }

    const int b = bh >> 3, h = bh & 7;
    const int r1 = wid*16 + g, r2 = r1 + 8;
    const float i1 = invs[r1], i2 = invs[r2];
    #pragma unroll
    for (int nt=0; nt<4; nt++) {
        int col = h*HD + nt*8 + t4*2;
        *(float2*)(g_attn + ((size_t)b*NN + n0+r1)*CC + col) = make_float2(acc[nt][0]*i1, acc[nt][1]*i1);
        *(float2*)(g_attn + ((size_t)b*NN + n0+r2)*CC + col) = make_float2(acc[nt][2]*i2, acc[nt][3]*i2);
    }
}

// ---------------- launch ----------------
#define SM_PROJ (2*(128*36*4 + 2*128*80))
#define SM_CONV (2*(64*36*4  + 2*256*80))
#define SM_ATTN (18432 + 2*34816 + 2*8704 + 2048 + 512 + 512)

extern "C" void kernel_launch(void* const* d_in, const int* in_sizes, int n_in,
                              void* d_out, int out_size)
{
    const float *query=0,*ipw=0,*ipb=0,*srw=0,*srb=0,*ng=0,*nb=0,*outw=0,*outb=0,*sew1=0,*sew2=0;
    int nbig = 0, n256 = 0, n32k = 0;
    for (int i = 0; i < n_in; i++) {
        const int s = in_sizes[i];
        const float* p = (const float*)d_in[i];
        if (s == 16777216)      { if (nbig++ == 0) query = p; }
        else if (s == 196608)   ipw = p;
        else if (s == 768)      ipb = p;
        else if (s == 262144)   srw = p;
        else if (s == 65536)    outw = p;
        else if (s == 32768)    { if (n32k++ == 0) sew1 = p; else sew2 = p; }
        else if (s == 256) {
            switch (n256++) {
                case 0: srb = p; break;
                case 1: ng  = p; break;
                case 2: nb  = p; break;
                case 3: outb= p; break;
            }
        }
    }
    float* out = (float*)d_out;

    cudaFuncSetAttribute(mm_tc<3,4,0,64,256,1024,8>,  cudaFuncAttributeMaxDynamicSharedMemorySize, SM_CONV);
    cudaFuncSetAttribute(mm_tc<0,2,0,128,128,256,10>, cudaFuncAttributeMaxDynamicSharedMemorySize, SM_PROJ);
    cudaFuncSetAttribute(mm_tc<1,5,1,128,128,256,8>,  cudaFuncAttributeMaxDynamicSharedMemorySize, SM_PROJ);
    cudaFuncSetAttribute(mm_tc<2,3,3,128,128,256,10>, cudaFuncAttributeMaxDynamicSharedMemorySize, SM_PROJ);
    cudaFuncSetAttribute(attn_tc, cudaFuncAttributeMaxDynamicSharedMemorySize, SM_ATTN);

    prep_kernel<<<2048, 256>>>(ipw, outw, srw);
    se_kernel<<<BB, 256>>>(query, sew1, sew2);
    // conv + LN  (M=16384 rows of 64)
    mm_tc<3,4,0,64,256,1024,8><<<256, 256, SM_CONV>>>(query, srb, ng, nb, nullptr);
    // q proj (M=65536)
    mm_tc<0,2,0,128,128,256,10><<<dim3(512,2), 256, SM_PROJ>>>(query, ipb, nullptr, nullptr, nullptr);
    // fused k+v proj (M=16384, N=512)
    mm_tc<1,5,1,128,128,256,8><<<dim3(128,4), 256, SM_PROJ>>>(nullptr, ipb + CC, nullptr, nullptr, nullptr);
    kv_kernel<<<NBH, 256>>>();
    attn_tc<<<dim3(8, NBH), 256, SM_ATTN>>>();
    // out proj (M=65536)
    mm_tc<2,3,3,128,128,256,10><<<dim3(512,2), 256, SM_PROJ>>>(nullptr, outb, nullptr, nullptr, out);
    (void)out_size;
}